// round 1
// baseline (speedup 1.0000x reference)
#include <cuda_runtime.h>
#include <math.h>

#define BATCH   4
#define SEQLEN  2048
#define NHEADS  16
#define HDIM    64
#define DIM     1024
#define MTOT    (BATCH * SEQLEN)   // 8192

// ---------------- scratch (static __device__, no allocs allowed) -------------
__device__ float g_q[MTOT * DIM];
__device__ float g_k[MTOT * DIM];
__device__ float g_v[MTOT * DIM];
__device__ float g_a[MTOT * DIM];

// ---------------- GEMM: C[m][n] = sum_k A[m][k] * B[n][k]  (NT) --------------
// A: [M, K] row-major, B: [N, K] row-major (weights are [out, in] => x @ W^T)
// Tiles: 128x128x16, 256 threads, 8x8 microtile.
#define GBM 128
#define GBN 128
#define GBK 16
#define GPAD 4   // SMEM pad: stride 132 floats, keeps float4 16B-aligned

__global__ void __launch_bounds__(256, 2)
gemm_nt(const float* __restrict__ A,
        const float* __restrict__ B0, const float* __restrict__ B1, const float* __restrict__ B2,
        float* __restrict__ C0, float* __restrict__ C1, float* __restrict__ C2)
{
    const float* __restrict__ B = (blockIdx.z == 0) ? B0 : (blockIdx.z == 1 ? B1 : B2);
    float* __restrict__ C       = (blockIdx.z == 0) ? C0 : (blockIdx.z == 1 ? C1 : C2);

    const int K = DIM;
    const int N = DIM;

    __shared__ float As[GBK][GBM + GPAD];
    __shared__ float Bs[GBK][GBN + GPAD];

    const int tid = threadIdx.x;
    const int tx = tid & 15;        // 0..15  (n direction)
    const int ty = tid >> 4;        // 0..15  (m direction)
    const int m0 = blockIdx.y * GBM;
    const int n0 = blockIdx.x * GBN;

    const int lr = tid >> 2;        // 0..63
    const int lc = (tid & 3) << 2;  // 0,4,8,12

    float acc[8][8];
#pragma unroll
    for (int i = 0; i < 8; i++)
#pragma unroll
        for (int j = 0; j < 8; j++) acc[i][j] = 0.f;

    for (int k0 = 0; k0 < K; k0 += GBK) {
#pragma unroll
        for (int h = 0; h < 2; h++) {
            const int r = lr + 64 * h;
            float4 va = *(const float4*)(A + (size_t)(m0 + r) * K + k0 + lc);
            As[lc + 0][r] = va.x; As[lc + 1][r] = va.y;
            As[lc + 2][r] = va.z; As[lc + 3][r] = va.w;
            float4 vb = *(const float4*)(B + (size_t)(n0 + r) * K + k0 + lc);
            Bs[lc + 0][r] = vb.x; Bs[lc + 1][r] = vb.y;
            Bs[lc + 2][r] = vb.z; Bs[lc + 3][r] = vb.w;
        }
        __syncthreads();

#pragma unroll
        for (int k = 0; k < GBK; k++) {
            float ra[8], rb[8];
            *(float4*)&ra[0] = *(const float4*)&As[k][ty * 8];
            *(float4*)&ra[4] = *(const float4*)&As[k][ty * 8 + 4];
            *(float4*)&rb[0] = *(const float4*)&Bs[k][tx * 8];
            *(float4*)&rb[4] = *(const float4*)&Bs[k][tx * 8 + 4];
#pragma unroll
            for (int i = 0; i < 8; i++)
#pragma unroll
                for (int j = 0; j < 8; j++)
                    acc[i][j] = fmaf(ra[i], rb[j], acc[i][j]);
        }
        __syncthreads();
    }

#pragma unroll
    for (int i = 0; i < 8; i++) {
        float* cp = C + (size_t)(m0 + ty * 8 + i) * N + n0 + tx * 8;
        *(float4*)cp       = make_float4(acc[i][0], acc[i][1], acc[i][2], acc[i][3]);
        *(float4*)(cp + 4) = make_float4(acc[i][4], acc[i][5], acc[i][6], acc[i][7]);
    }
}

// ---------------- Flash attention with diagonal mask -------------------------
// Q/K/V layout: [B, L, H, D]  (element (b,l,h,d) at ((b*L+l)*H + h)*D + d)
// Grid: (L/BQ, B*H). Block: 256 threads (tx = key/d dir 0..15, ty = query dir 0..15).
#define BQ 128
#define BS 64
#define QS_STRIDE 68   // float4-aligned pad
#define KS_STRIDE 68
#define PS_STRIDE 68
#define ATTN_SMEM_FLOATS (BQ * QS_STRIDE + BS * KS_STRIDE + BS * 64 + BQ * PS_STRIDE)
#define ATTN_SMEM_BYTES  (ATTN_SMEM_FLOATS * 4)

__global__ void __launch_bounds__(256, 2)
attn_kernel(const float* __restrict__ Qg, const float* __restrict__ Kg,
            const float* __restrict__ Vg, float* __restrict__ Og)
{
    extern __shared__ float sm[];
    float* Qs = sm;                        // [BQ][68]
    float* Ks = Qs + BQ * QS_STRIDE;       // [BS][68]
    float* Vs = Ks + BS * KS_STRIDE;       // [BS][64]
    float* Ps = Vs + BS * 64;              // [BQ][68]

    const int tid = threadIdx.x;
    const int tx = tid & 15;
    const int ty = tid >> 4;
    const int q0 = blockIdx.x * BQ;
    const int bh = blockIdx.y;
    const int b  = bh >> 4;
    const int h  = bh & 15;
    const float scale = 0.125f;            // 1/sqrt(64)

    const size_t rowstride = (size_t)NHEADS * HDIM;                 // 1024
    const size_t base = ((size_t)b * SEQLEN) * rowstride + (size_t)h * HDIM;

    // ---- load Q tile [BQ][64] into SMEM (float4, coalesced 256B rows) ----
    {
        const int c = tx * 4;
#pragma unroll
        for (int rr = 0; rr < 8; rr++) {
            const int r = ty + rr * 16;
            float4 v = *(const float4*)(Qg + base + (size_t)(q0 + r) * rowstride + c);
            *(float4*)&Qs[r * QS_STRIDE + c] = v;
        }
    }

    float m[8], l[8], O[8][4];
#pragma unroll
    for (int i = 0; i < 8; i++) {
        m[i] = -1e30f; l[i] = 0.f;
#pragma unroll
        for (int j = 0; j < 4; j++) O[i][j] = 0.f;
    }
    __syncthreads();

    for (int s0 = 0; s0 < SEQLEN; s0 += BS) {
        // ---- load K,V tiles [BS][64] ----
        {
            const int c = tx * 4;
#pragma unroll
            for (int rr = 0; rr < 4; rr++) {
                const int r = ty + rr * 16;
                float4 kv = *(const float4*)(Kg + base + (size_t)(s0 + r) * rowstride + c);
                *(float4*)&Ks[r * KS_STRIDE + c] = kv;
                float4 vv = *(const float4*)(Vg + base + (size_t)(s0 + r) * rowstride + c);
                *(float4*)&Vs[r * 64 + c] = vv;
            }
        }
        __syncthreads();

        // ---- S = Q @ K^T  (each thread: 8 q-rows x 4 keys) ----
        float acc[8][4];
#pragma unroll
        for (int i = 0; i < 8; i++)
#pragma unroll
            for (int j = 0; j < 4; j++) acc[i][j] = 0.f;

#pragma unroll
        for (int d = 0; d < HDIM; d += 4) {
            float4 rk[4];
#pragma unroll
            for (int j = 0; j < 4; j++)
                rk[j] = *(const float4*)&Ks[(tx * 4 + j) * KS_STRIDE + d];
#pragma unroll
            for (int i = 0; i < 8; i++) {
                float4 q = *(const float4*)&Qs[(ty * 8 + i) * QS_STRIDE + d];
                acc[i][0] += q.x * rk[0].x + q.y * rk[0].y + q.z * rk[0].z + q.w * rk[0].w;
                acc[i][1] += q.x * rk[1].x + q.y * rk[1].y + q.z * rk[1].z + q.w * rk[1].w;
                acc[i][2] += q.x * rk[2].x + q.y * rk[2].y + q.z * rk[2].z + q.w * rk[2].w;
                acc[i][3] += q.x * rk[3].x + q.y * rk[3].y + q.z * rk[3].z + q.w * rk[3].w;
            }
        }

        // ---- scale + diagonal mask + online softmax update ----
#pragma unroll
        for (int i = 0; i < 8; i++) {
            const int qg = q0 + ty * 8 + i;
            float vmax = -1e30f;
#pragma unroll
            for (int j = 0; j < 4; j++) {
                const int kg = s0 + tx * 4 + j;
                float s = acc[i][j] * scale;
                if (kg == qg) s = -1e30f;   // exclude self
                acc[i][j] = s;
                vmax = fmaxf(vmax, s);
            }
            // reduce max across the 16 tx-lanes sharing this row
#pragma unroll
            for (int off = 8; off >= 1; off >>= 1)
                vmax = fmaxf(vmax, __shfl_xor_sync(0xffffffffu, vmax, off));

            const float mn = fmaxf(m[i], vmax);
            const float corr = __expf(m[i] - mn);   // m=-1e30 -> underflow to 0
            m[i] = mn;

            float rs = 0.f;
#pragma unroll
            for (int j = 0; j < 4; j++) {
                float p = __expf(acc[i][j] - mn);   // masked -> exp(-1e30) = 0
                acc[i][j] = p;
                rs += p;
            }
#pragma unroll
            for (int off = 8; off >= 1; off >>= 1)
                rs += __shfl_xor_sync(0xffffffffu, rs, off);

            l[i] = l[i] * corr + rs;
#pragma unroll
            for (int j = 0; j < 4; j++) O[i][j] *= corr;

            // stage P into SMEM for the PV GEMM
#pragma unroll
            for (int j = 0; j < 4; j++)
                Ps[(ty * 8 + i) * PS_STRIDE + tx * 4 + j] = acc[i][j];
        }
        __syncthreads();

        // ---- O += P @ V  (each thread: 8 q-rows x 4 d-cols) ----
#pragma unroll
        for (int s = 0; s < BS; s += 4) {
            float4 rv[4];
#pragma unroll
            for (int u = 0; u < 4; u++)
                rv[u] = *(const float4*)&Vs[(s + u) * 64 + tx * 4];
#pragma unroll
            for (int i = 0; i < 8; i++) {
                float4 p = *(const float4*)&Ps[(ty * 8 + i) * PS_STRIDE + s];
                O[i][0] += p.x * rv[0].x + p.y * rv[1].x + p.z * rv[2].x + p.w * rv[3].x;
                O[i][1] += p.x * rv[0].y + p.y * rv[1].y + p.z * rv[2].y + p.w * rv[3].y;
                O[i][2] += p.x * rv[0].z + p.y * rv[1].z + p.z * rv[2].z + p.w * rv[3].z;
                O[i][3] += p.x * rv[0].w + p.y * rv[1].w + p.z * rv[2].w + p.w * rv[3].w;
            }
        }
        __syncthreads();   // before next tile overwrites Ks/Vs/Ps
    }

    // ---- finalize and write O ----
#pragma unroll
    for (int i = 0; i < 8; i++) {
        const float inv = 1.f / l[i];
        float4 o = make_float4(O[i][0] * inv, O[i][1] * inv, O[i][2] * inv, O[i][3] * inv);
        *(float4*)&Og[base + (size_t)(q0 + ty * 8 + i) * rowstride + tx * 4] = o;
    }
}

// ---------------- launch ------------------------------------------------------
extern "C" void kernel_launch(void* const* d_in, const int* in_sizes, int n_in,
                              void* d_out, int out_size)
{
    (void)in_sizes; (void)n_in; (void)out_size;
    const float* x  = (const float*)d_in[0];
    const float* wq = (const float*)d_in[1];
    const float* wk = (const float*)d_in[2];
    const float* wv = (const float*)d_in[3];
    const float* wo = (const float*)d_in[4];
    float* out = (float*)d_out;

    float *qp, *kp, *vp, *ap;
    cudaGetSymbolAddress((void**)&qp, g_q);
    cudaGetSymbolAddress((void**)&kp, g_k);
    cudaGetSymbolAddress((void**)&vp, g_v);
    cudaGetSymbolAddress((void**)&ap, g_a);

    cudaFuncSetAttribute(attn_kernel, cudaFuncAttributeMaxDynamicSharedMemorySize,
                         ATTN_SMEM_BYTES);

    // 1) QKV projections (fused via grid.z)
    {
        dim3 grid(DIM / GBN, MTOT / GBM, 3);
        gemm_nt<<<grid, 256>>>(x, wq, wk, wv, qp, kp, vp);
    }
    // 2) attention
    {
        dim3 grid(SEQLEN / BQ, BATCH * NHEADS);
        attn_kernel<<<grid, 256, ATTN_SMEM_BYTES>>>(qp, kp, vp, ap);
    }
    // 3) output projection
    {
        dim3 grid(DIM / GBN, MTOT / GBM, 1);
        gemm_nt<<<grid, 256>>>(ap, wo, wo, wo, out, out, out);
    }
}

// round 2
// speedup vs baseline: 1.2106x; 1.2106x over previous
#include <cuda_runtime.h>
#include <math.h>
#include <stdint.h>

#define BATCH   4
#define SEQLEN  2048
#define NHEADS  16
#define HDIM    64
#define DIM     1024
#define MTOT    (BATCH * SEQLEN)   // 8192

// ---------------- scratch (static __device__, no allocs allowed) -------------
__device__ float g_q[MTOT * DIM];
__device__ float g_k[MTOT * DIM];
__device__ float g_v[MTOT * DIM];
__device__ float g_a[MTOT * DIM];

// ---------------- tf32 helpers ----------------------------------------------
__device__ __forceinline__ uint32_t f2tf32(float x) {
    uint32_t r; asm("cvt.rna.tf32.f32 %0, %1;" : "=r"(r) : "f"(x)); return r;
}
__device__ __forceinline__ void split_tf32(float x, uint32_t& hi, uint32_t& lo) {
    hi = f2tf32(x);
    float l = x - __uint_as_float(hi);
    lo = f2tf32(l);
}
// D += A*B for one m16n8k8 tf32 tile
__device__ __forceinline__ void mma8(float* d, const uint32_t* a, const uint32_t* b) {
    asm volatile(
        "mma.sync.aligned.m16n8k8.row.col.f32.tf32.tf32.f32 "
        "{%0,%1,%2,%3}, {%4,%5,%6,%7}, {%8,%9}, {%0,%1,%2,%3};"
        : "+f"(d[0]), "+f"(d[1]), "+f"(d[2]), "+f"(d[3])
        : "r"(a[0]), "r"(a[1]), "r"(a[2]), "r"(a[3]), "r"(b[0]), "r"(b[1]));
}

// ---------------- GEMM: C[m][n] = sum_k A[m][k] * B[n][k]  (NT) --------------
// CTA tile 128x128x16, 8 warps of 64x32, tf32x3 mma.
#define GBM 128
#define GBN 128
#define GBK 16
#define ASTR 132   // SMEM row stride (floats): k-major [GBK][128+4]

__global__ void __launch_bounds__(256)
gemm_nt(const float* __restrict__ A,
        const float* __restrict__ B0, const float* __restrict__ B1, const float* __restrict__ B2,
        float* __restrict__ C0, float* __restrict__ C1, float* __restrict__ C2)
{
    const float* __restrict__ B = (blockIdx.z == 0) ? B0 : (blockIdx.z == 1 ? B1 : B2);
    float* __restrict__ C       = (blockIdx.z == 0) ? C0 : (blockIdx.z == 1 ? C1 : C2);

    const int K = DIM;
    const int N = DIM;

    __shared__ float As[GBK][ASTR];
    __shared__ float Bs[GBK][ASTR];

    const int tid  = threadIdx.x;
    const int wid  = tid >> 5;
    const int lane = tid & 31;
    const int g    = lane >> 2;     // groupID 0..7
    const int t    = lane & 3;      // tid-in-group 0..3
    const int wm   = wid >> 2;      // 0..1 -> 64-row slab
    const int wn   = wid & 3;       // 0..3 -> 32-col slab
    const int m0   = blockIdx.y * GBM;
    const int n0   = blockIdx.x * GBN;

    const int lr = tid >> 2;        // 0..63
    const int lc = (tid & 3) << 2;  // 0,4,8,12

    float acc[4][4][4];             // [mi][nj][frag]
#pragma unroll
    for (int i = 0; i < 4; i++)
#pragma unroll
        for (int j = 0; j < 4; j++)
#pragma unroll
            for (int c = 0; c < 4; c++) acc[i][j][c] = 0.f;

    for (int k0 = 0; k0 < K; k0 += GBK) {
#pragma unroll
        for (int h = 0; h < 2; h++) {
            const int r = lr + 64 * h;
            float4 va = *(const float4*)(A + (size_t)(m0 + r) * K + k0 + lc);
            As[lc + 0][r] = va.x; As[lc + 1][r] = va.y;
            As[lc + 2][r] = va.z; As[lc + 3][r] = va.w;
            float4 vb = *(const float4*)(B + (size_t)(n0 + r) * K + k0 + lc);
            Bs[lc + 0][r] = vb.x; Bs[lc + 1][r] = vb.y;
            Bs[lc + 2][r] = vb.z; Bs[lc + 3][r] = vb.w;
        }
        __syncthreads();

#pragma unroll
        for (int ks = 0; ks < 2; ks++) {
            const int kk = ks * 8;
            uint32_t ahi[4][4], alo[4][4];
#pragma unroll
            for (int mi = 0; mi < 4; mi++) {
                const int rb = wm * 64 + mi * 16;
                float a0 = As[kk + t][rb + g];
                float a1 = As[kk + t][rb + g + 8];
                float a2 = As[kk + t + 4][rb + g];
                float a3 = As[kk + t + 4][rb + g + 8];
                split_tf32(a0, ahi[mi][0], alo[mi][0]);
                split_tf32(a1, ahi[mi][1], alo[mi][1]);
                split_tf32(a2, ahi[mi][2], alo[mi][2]);
                split_tf32(a3, ahi[mi][3], alo[mi][3]);
            }
#pragma unroll
            for (int nj = 0; nj < 4; nj++) {
                const int cb = wn * 32 + nj * 8;
                float b0 = Bs[kk + t][cb + g];
                float b1 = Bs[kk + t + 4][cb + g];
                uint32_t bhi[2], blo[2];
                split_tf32(b0, bhi[0], blo[0]);
                split_tf32(b1, bhi[1], blo[1]);
#pragma unroll
                for (int mi = 0; mi < 4; mi++) {
                    mma8(acc[mi][nj], ahi[mi], bhi);
                    mma8(acc[mi][nj], alo[mi], bhi);
                    mma8(acc[mi][nj], ahi[mi], blo);
                }
            }
        }
        __syncthreads();
    }

#pragma unroll
    for (int mi = 0; mi < 4; mi++) {
#pragma unroll
        for (int nj = 0; nj < 4; nj++) {
            const int row = m0 + wm * 64 + mi * 16 + g;
            const int col = n0 + wn * 32 + nj * 8 + 2 * t;
            *(float2*)(C + (size_t)row * N + col)       = make_float2(acc[mi][nj][0], acc[mi][nj][1]);
            *(float2*)(C + (size_t)(row + 8) * N + col) = make_float2(acc[mi][nj][2], acc[mi][nj][3]);
        }
    }
}

// ---------------- Flash attention (tf32x3 mma) with diagonal mask ------------
// Q/K/V layout: [B, L, H, D]. Grid: (L/BQ, B*H). Block 256 = 8 warps,
// warp w owns query rows [w*16, w*16+16).
#define BQ 128
#define BS 64
#define STR 68
#define ATTN_SMEM_FLOATS (BQ * STR + BS * STR + BS * STR + 8 * 16 * STR)
#define ATTN_SMEM_BYTES  (ATTN_SMEM_FLOATS * 4)

__global__ void __launch_bounds__(256)
attn_kernel(const float* __restrict__ Qg, const float* __restrict__ Kg,
            const float* __restrict__ Vg, float* __restrict__ Og)
{
    extern __shared__ float smf[];
    float* Qs = smf;                  // [128][68]
    float* Ks = Qs + BQ * STR;        // [64][68]
    float* Vs = Ks + BS * STR;        // [64][68]
    float* Ps = Vs + BS * STR;        // 8 warps x [16][68]

    const int tid  = threadIdx.x;
    const int wid  = tid >> 5;
    const int lane = tid & 31;
    const int g    = lane >> 2;
    const int t    = lane & 3;
    const int tx   = tid & 15;
    const int ty   = tid >> 4;
    const int q0   = blockIdx.x * BQ;
    const int bh   = blockIdx.y;
    const int b    = bh >> 4;
    const int h    = bh & 15;
    const float scale = 0.125f;

    const size_t rowstride = (size_t)NHEADS * HDIM;  // 1024
    const size_t base = ((size_t)b * SEQLEN) * rowstride + (size_t)h * HDIM;

    // load Q tile [BQ][64]
    {
        const int c = tx * 4;
#pragma unroll
        for (int rr = 0; rr < 8; rr++) {
            const int r = ty + rr * 16;
            float4 v = *(const float4*)(Qg + base + (size_t)(q0 + r) * rowstride + c);
            *(float4*)&Qs[r * STR + c] = v;
        }
    }

    float mrow[2], lrow[2], O[8][4];
    mrow[0] = mrow[1] = -1e30f;
    lrow[0] = lrow[1] = 0.f;
#pragma unroll
    for (int nt = 0; nt < 8; nt++)
#pragma unroll
        for (int c = 0; c < 4; c++) O[nt][c] = 0.f;

    float* PsW = Ps + wid * 16 * STR;
    const int rq = wid * 16;          // warp's first query row in tile
    __syncthreads();

    for (int s0 = 0; s0 < SEQLEN; s0 += BS) {
        // load K,V tiles [BS][64]
        {
            const int c = tx * 4;
#pragma unroll
            for (int rr = 0; rr < 4; rr++) {
                const int r = ty + rr * 16;
                float4 kv = *(const float4*)(Kg + base + (size_t)(s0 + r) * rowstride + c);
                *(float4*)&Ks[r * STR + c] = kv;
                float4 vv = *(const float4*)(Vg + base + (size_t)(s0 + r) * rowstride + c);
                *(float4*)&Vs[r * STR + c] = vv;
            }
        }
        __syncthreads();

        // ---- S = Q @ K^T via tf32x3 mma ----
        float S[8][4];
#pragma unroll
        for (int nt = 0; nt < 8; nt++)
#pragma unroll
            for (int c = 0; c < 4; c++) S[nt][c] = 0.f;

#pragma unroll
        for (int ks = 0; ks < 8; ks++) {
            const int kk = ks * 8;
            uint32_t ahi[4], alo[4];
            split_tf32(Qs[(rq + g) * STR + kk + t],     ahi[0], alo[0]);
            split_tf32(Qs[(rq + g + 8) * STR + kk + t], ahi[1], alo[1]);
            split_tf32(Qs[(rq + g) * STR + kk + t + 4], ahi[2], alo[2]);
            split_tf32(Qs[(rq + g + 8) * STR + kk + t + 4], ahi[3], alo[3]);
#pragma unroll
            for (int nt = 0; nt < 8; nt++) {
                uint32_t bhi[2], blo[2];
                split_tf32(Ks[(nt * 8 + g) * STR + kk + t],     bhi[0], blo[0]);
                split_tf32(Ks[(nt * 8 + g) * STR + kk + t + 4], bhi[1], blo[1]);
                mma8(S[nt], ahi, bhi);
                mma8(S[nt], alo, bhi);
                mma8(S[nt], ahi, blo);
            }
        }

        // ---- scale + diagonal mask ----
#pragma unroll
        for (int nt = 0; nt < 8; nt++) {
#pragma unroll
            for (int c = 0; c < 4; c++) {
                const int col = s0 + nt * 8 + 2 * t + (c & 1);
                const int row = q0 + rq + g + ((c >= 2) ? 8 : 0);
                float s = S[nt][c] * scale;
                if (col == row) s = -1e30f;
                S[nt][c] = s;
            }
        }

        // ---- online softmax (rows g and g+8) ----
        float mx0 = -1e30f, mx1 = -1e30f;
#pragma unroll
        for (int nt = 0; nt < 8; nt++) {
            mx0 = fmaxf(mx0, fmaxf(S[nt][0], S[nt][1]));
            mx1 = fmaxf(mx1, fmaxf(S[nt][2], S[nt][3]));
        }
        mx0 = fmaxf(mx0, __shfl_xor_sync(0xffffffffu, mx0, 1));
        mx0 = fmaxf(mx0, __shfl_xor_sync(0xffffffffu, mx0, 2));
        mx1 = fmaxf(mx1, __shfl_xor_sync(0xffffffffu, mx1, 1));
        mx1 = fmaxf(mx1, __shfl_xor_sync(0xffffffffu, mx1, 2));

        const float mn0 = fmaxf(mrow[0], mx0);
        const float mn1 = fmaxf(mrow[1], mx1);
        const float corr0 = __expf(mrow[0] - mn0);
        const float corr1 = __expf(mrow[1] - mn1);
        mrow[0] = mn0; mrow[1] = mn1;

        float rs0 = 0.f, rs1 = 0.f;
#pragma unroll
        for (int nt = 0; nt < 8; nt++) {
            float p0 = __expf(S[nt][0] - mn0);
            float p1 = __expf(S[nt][1] - mn0);
            float p2 = __expf(S[nt][2] - mn1);
            float p3 = __expf(S[nt][3] - mn1);
            S[nt][0] = p0; S[nt][1] = p1; S[nt][2] = p2; S[nt][3] = p3;
            rs0 += p0 + p1;
            rs1 += p2 + p3;
        }
        rs0 += __shfl_xor_sync(0xffffffffu, rs0, 1);
        rs0 += __shfl_xor_sync(0xffffffffu, rs0, 2);
        rs1 += __shfl_xor_sync(0xffffffffu, rs1, 1);
        rs1 += __shfl_xor_sync(0xffffffffu, rs1, 2);

        lrow[0] = lrow[0] * corr0 + rs0;
        lrow[1] = lrow[1] * corr1 + rs1;
#pragma unroll
        for (int nt = 0; nt < 8; nt++) {
            O[nt][0] *= corr0; O[nt][1] *= corr0;
            O[nt][2] *= corr1; O[nt][3] *= corr1;
        }

        // ---- stage P to per-warp SMEM for PV A-operand ----
#pragma unroll
        for (int nt = 0; nt < 8; nt++) {
            *(float2*)&PsW[g * STR + nt * 8 + 2 * t]       = make_float2(S[nt][0], S[nt][1]);
            *(float2*)&PsW[(g + 8) * STR + nt * 8 + 2 * t] = make_float2(S[nt][2], S[nt][3]);
        }
        __syncwarp();

        // ---- O += P @ V via tf32x3 mma ----
#pragma unroll
        for (int ks = 0; ks < 8; ks++) {
            const int kk = ks * 8;
            uint32_t ahi[4], alo[4];
            split_tf32(PsW[g * STR + kk + t],           ahi[0], alo[0]);
            split_tf32(PsW[(g + 8) * STR + kk + t],     ahi[1], alo[1]);
            split_tf32(PsW[g * STR + kk + t + 4],       ahi[2], alo[2]);
            split_tf32(PsW[(g + 8) * STR + kk + t + 4], ahi[3], alo[3]);
#pragma unroll
            for (int nt = 0; nt < 8; nt++) {
                uint32_t bhi[2], blo[2];
                split_tf32(Vs[(kk + t) * STR + nt * 8 + g],     bhi[0], blo[0]);
                split_tf32(Vs[(kk + t + 4) * STR + nt * 8 + g], bhi[1], blo[1]);
                mma8(O[nt], ahi, bhi);
                mma8(O[nt], alo, bhi);
                mma8(O[nt], ahi, blo);
            }
        }
        __syncthreads();   // before next tile overwrites Ks/Vs
    }

    // ---- finalize ----
    const float inv0 = 1.f / lrow[0];
    const float inv1 = 1.f / lrow[1];
#pragma unroll
    for (int nt = 0; nt < 8; nt++) {
        const int row = q0 + rq + g;
        const int col = nt * 8 + 2 * t;
        *(float2*)(Og + base + (size_t)row * rowstride + col) =
            make_float2(O[nt][0] * inv0, O[nt][1] * inv0);
        *(float2*)(Og + base + (size_t)(row + 8) * rowstride + col) =
            make_float2(O[nt][2] * inv1, O[nt][3] * inv1);
    }
}

// ---------------- launch ------------------------------------------------------
extern "C" void kernel_launch(void* const* d_in, const int* in_sizes, int n_in,
                              void* d_out, int out_size)
{
    (void)in_sizes; (void)n_in; (void)out_size;
    const float* x  = (const float*)d_in[0];
    const float* wq = (const float*)d_in[1];
    const float* wk = (const float*)d_in[2];
    const float* wv = (const float*)d_in[3];
    const float* wo = (const float*)d_in[4];
    float* out = (float*)d_out;

    float *qp, *kp, *vp, *ap;
    cudaGetSymbolAddress((void**)&qp, g_q);
    cudaGetSymbolAddress((void**)&kp, g_k);
    cudaGetSymbolAddress((void**)&vp, g_v);
    cudaGetSymbolAddress((void**)&ap, g_a);

    cudaFuncSetAttribute(attn_kernel, cudaFuncAttributeMaxDynamicSharedMemorySize,
                         ATTN_SMEM_BYTES);

    // 1) QKV projections (fused via grid.z)
    {
        dim3 grid(DIM / GBN, MTOT / GBM, 3);
        gemm_nt<<<grid, 256>>>(x, wq, wk, wv, qp, kp, vp);
    }
    // 2) attention
    {
        dim3 grid(SEQLEN / BQ, BATCH * NHEADS);
        attn_kernel<<<grid, 256, ATTN_SMEM_BYTES>>>(qp, kp, vp, ap);
    }
    // 3) output projection
    {
        dim3 grid(DIM / GBN, MTOT / GBM, 1);
        gemm_nt<<<grid, 256>>>(ap, wo, wo, wo, out, out, out);
    }
}

// round 5
// speedup vs baseline: 1.5415x; 1.2734x over previous
#include <cuda_runtime.h>
#include <math.h>
#include <stdint.h>

#define BATCH   4
#define SEQLEN  2048
#define NHEADS  16
#define HDIM    64
#define DIM     1024
#define MTOT    (BATCH * SEQLEN)   // 8192

// ---------------- scratch (static __device__, no allocs allowed) -------------
__device__ float g_q[MTOT * DIM];
__device__ float g_k[MTOT * DIM];
__device__ float g_v[MTOT * DIM];
__device__ float g_a[MTOT * DIM];

// ---------------- tf32 helpers ----------------------------------------------
__device__ __forceinline__ uint32_t f2tf32(float x) {
    uint32_t r; asm("cvt.rna.tf32.f32 %0, %1;" : "=r"(r) : "f"(x)); return r;
}
__device__ __forceinline__ void split_tf32(float x, uint32_t& hi, uint32_t& lo) {
    hi = f2tf32(x);
    float l = x - __uint_as_float(hi);
    lo = f2tf32(l);
}
__device__ __forceinline__ void mma8(float* d, const uint32_t* a, const uint32_t* b) {
    asm volatile(
        "mma.sync.aligned.m16n8k8.row.col.f32.tf32.tf32.f32 "
        "{%0,%1,%2,%3}, {%4,%5,%6,%7}, {%8,%9}, {%0,%1,%2,%3};"
        : "+f"(d[0]), "+f"(d[1]), "+f"(d[2]), "+f"(d[3])
        : "r"(a[0]), "r"(a[1]), "r"(a[2]), "r"(a[3]), "r"(b[0]), "r"(b[1]));
}

// ---------------- GEMM: C[m][n] = sum_k A[m][k] * B[n][k]  (NT) --------------
// CTA tile 128x128x16, 8 warps of 64x32, tf32x3, double-buffered pre-split SMEM.
#define GBM 128
#define GBN 128
#define GBK 16
#define ASTR 136                         // 136 mod 32 = 8 -> conflict-free frags
#define GSS  (4 * GBK * ASTR)            // floats per stage (Ahi,Alo,Bhi,Blo)
#define GEMM_SMEM_BYTES (2 * GSS * 4)

__device__ __forceinline__ void store_split4(float* hi, float* lo, int k, int r, float4 v) {
    uint32_t h, l;
    split_tf32(v.x, h, l); hi[(k+0)*ASTR + r] = __uint_as_float(h); lo[(k+0)*ASTR + r] = __uint_as_float(l);
    split_tf32(v.y, h, l); hi[(k+1)*ASTR + r] = __uint_as_float(h); lo[(k+1)*ASTR + r] = __uint_as_float(l);
    split_tf32(v.z, h, l); hi[(k+2)*ASTR + r] = __uint_as_float(h); lo[(k+2)*ASTR + r] = __uint_as_float(l);
    split_tf32(v.w, h, l); hi[(k+3)*ASTR + r] = __uint_as_float(h); lo[(k+3)*ASTR + r] = __uint_as_float(l);
}

__global__ void __launch_bounds__(256, 2)
gemm_nt(const float* __restrict__ A,
        const float* __restrict__ B0, const float* __restrict__ B1, const float* __restrict__ B2,
        float* __restrict__ C0, float* __restrict__ C1, float* __restrict__ C2)
{
    const float* __restrict__ B = (blockIdx.z == 0) ? B0 : (blockIdx.z == 1 ? B1 : B2);
    float* __restrict__ C       = (blockIdx.z == 0) ? C0 : (blockIdx.z == 1 ? C1 : C2);

    extern __shared__ float gsm[];
    const int K = DIM;
    const int N = DIM;

    const int tid  = threadIdx.x;
    const int lane = tid & 31;
    const int wid  = tid >> 5;
    const int g    = lane >> 2;
    const int t    = lane & 3;
    const int wm   = wid >> 2;
    const int wn   = wid & 3;
    const int m0   = blockIdx.y * GBM;
    const int n0   = blockIdx.x * GBN;

    const int lr = tid >> 2;
    const int lc = (tid & 3) << 2;

    const float* Ag0 = A + (size_t)(m0 + lr) * K + lc;
    const float* Ag1 = A + (size_t)(m0 + lr + 64) * K + lc;
    const float* Bg0 = B + (size_t)(n0 + lr) * K + lc;
    const float* Bg1 = B + (size_t)(n0 + lr + 64) * K + lc;

    float acc[4][4][4];
#pragma unroll
    for (int i = 0; i < 4; i++)
#pragma unroll
        for (int j = 0; j < 4; j++)
#pragma unroll
            for (int c = 0; c < 4; c++) acc[i][j][c] = 0.f;

    const int NT = K / GBK;

    // prologue: tile 0
    {
        float4 va0 = *(const float4*)(Ag0);
        float4 va1 = *(const float4*)(Ag1);
        float4 vb0 = *(const float4*)(Bg0);
        float4 vb1 = *(const float4*)(Bg1);
        float* Ahi = gsm;            float* Alo = gsm + GBK * ASTR;
        float* Bhi = gsm + 2 * GBK * ASTR; float* Blo = gsm + 3 * GBK * ASTR;
        store_split4(Ahi, Alo, lc, lr,      va0);
        store_split4(Ahi, Alo, lc, lr + 64, va1);
        store_split4(Bhi, Blo, lc, lr,      vb0);
        store_split4(Bhi, Blo, lc, lr + 64, vb1);
    }
    __syncthreads();

    for (int kt = 0; kt < NT; kt++) {
        const int cur = kt & 1;
        const bool has = (kt + 1 < NT);
        float4 va0, va1, vb0, vb1;
        if (has) {
            const int ko = (kt + 1) * GBK;
            va0 = *(const float4*)(Ag0 + ko);
            va1 = *(const float4*)(Ag1 + ko);
            vb0 = *(const float4*)(Bg0 + ko);
            vb1 = *(const float4*)(Bg1 + ko);
        }

        const float* Ahi = gsm + cur * GSS;
        const float* Alo = Ahi + GBK * ASTR;
        const float* Bhi = Ahi + 2 * GBK * ASTR;
        const float* Blo = Ahi + 3 * GBK * ASTR;

#pragma unroll
        for (int ks = 0; ks < 2; ks++) {
            const int kk = ks * 8;
            uint32_t ahi[4][4], alo[4][4];
#pragma unroll
            for (int mi = 0; mi < 4; mi++) {
                const int rb = wm * 64 + mi * 16 + g;
                ahi[mi][0] = __float_as_uint(Ahi[(kk + t) * ASTR + rb]);
                ahi[mi][1] = __float_as_uint(Ahi[(kk + t) * ASTR + rb + 8]);
                ahi[mi][2] = __float_as_uint(Ahi[(kk + t + 4) * ASTR + rb]);
                ahi[mi][3] = __float_as_uint(Ahi[(kk + t + 4) * ASTR + rb + 8]);
                alo[mi][0] = __float_as_uint(Alo[(kk + t) * ASTR + rb]);
                alo[mi][1] = __float_as_uint(Alo[(kk + t) * ASTR + rb + 8]);
                alo[mi][2] = __float_as_uint(Alo[(kk + t + 4) * ASTR + rb]);
                alo[mi][3] = __float_as_uint(Alo[(kk + t + 4) * ASTR + rb + 8]);
            }
#pragma unroll
            for (int nj = 0; nj < 4; nj++) {
                const int cb = wn * 32 + nj * 8 + g;
                uint32_t bhi[2], blo[2];
                bhi[0] = __float_as_uint(Bhi[(kk + t) * ASTR + cb]);
                bhi[1] = __float_as_uint(Bhi[(kk + t + 4) * ASTR + cb]);
                blo[0] = __float_as_uint(Blo[(kk + t) * ASTR + cb]);
                blo[1] = __float_as_uint(Blo[(kk + t + 4) * ASTR + cb]);
                // pass-major inside nj: dependent mmas to same acc are 4 apart
#pragma unroll
                for (int mi = 0; mi < 4; mi++) mma8(acc[mi][nj], ahi[mi], bhi);
#pragma unroll
                for (int mi = 0; mi < 4; mi++) mma8(acc[mi][nj], alo[mi], bhi);
#pragma unroll
                for (int mi = 0; mi < 4; mi++) mma8(acc[mi][nj], ahi[mi], blo);
            }
        }

        if (has) {
            float* nAhi = gsm + (cur ^ 1) * GSS;
            float* nAlo = nAhi + GBK * ASTR;
            float* nBhi = nAhi + 2 * GBK * ASTR;
            float* nBlo = nAhi + 3 * GBK * ASTR;
            store_split4(nAhi, nAlo, lc, lr,      va0);
            store_split4(nAhi, nAlo, lc, lr + 64, va1);
            store_split4(nBhi, nBlo, lc, lr,      vb0);
            store_split4(nBhi, nBlo, lc, lr + 64, vb1);
        }
        __syncthreads();
    }

#pragma unroll
    for (int mi = 0; mi < 4; mi++) {
#pragma unroll
        for (int nj = 0; nj < 4; nj++) {
            const int row = m0 + wm * 64 + mi * 16 + g;
            const int col = n0 + wn * 32 + nj * 8 + 2 * t;
            *(float2*)(C + (size_t)row * N + col)       = make_float2(acc[mi][nj][0], acc[mi][nj][1]);
            *(float2*)(C + (size_t)(row + 8) * N + col) = make_float2(acc[mi][nj][2], acc[mi][nj][3]);
        }
    }
}

// ---------------- Flash attention (tf32x3 mma) with diagonal mask ------------
// Grid: (L/BQ, B*H). 8 warps; warp w owns query rows [w*16, w*16+16).
#define BQ 128
#define BS 64
#define QSTR 76   // g-row-indexed loads conflict-free (76 mod 32 = 12)
#define KSTR 76
#define VSTR 72   // t-row-indexed loads conflict-free (72 mod 32 = 8)
#define ATTN_SMEM_FLOATS (BQ * QSTR + 2 * BS * KSTR + 2 * BS * VSTR)
#define ATTN_SMEM_BYTES  (ATTN_SMEM_FLOATS * 4)

__global__ void __launch_bounds__(256, 2)
attn_kernel(const float* __restrict__ Qg, const float* __restrict__ Kg,
            const float* __restrict__ Vg, float* __restrict__ Og)
{
    extern __shared__ float smf[];
    float* Qs  = smf;                        // raw [128][QSTR]
    float* Khi = Qs  + BQ * QSTR;            // [64][KSTR]
    float* Klo = Khi + BS * KSTR;
    float* Vhi = Klo + BS * KSTR;            // [64][VSTR]
    float* Vlo = Vhi + BS * VSTR;

    const int tid  = threadIdx.x;
    const int lane = tid & 31;
    const int wid  = tid >> 5;
    const int g    = lane >> 2;
    const int t    = lane & 3;
    const int tx   = tid & 15;
    const int ty   = tid >> 4;
    const int q0   = blockIdx.x * BQ;
    const int bh   = blockIdx.y;
    const int b    = bh >> 4;
    const int h    = bh & 15;
    const float scale = 0.125f;

    const size_t rowstride = (size_t)NHEADS * HDIM;  // 1024
    const size_t base = ((size_t)b * SEQLEN) * rowstride + (size_t)h * HDIM;

    // load Q tile [BQ][64] (raw)
    {
        const int c = tx * 4;
#pragma unroll
        for (int rr = 0; rr < 8; rr++) {
            const int r = ty + rr * 16;
            float4 v = *(const float4*)(Qg + base + (size_t)(q0 + r) * rowstride + c);
            *(float4*)&Qs[r * QSTR + c] = v;
        }
    }

    float mrow[2], lrow[2], O[8][4];
    mrow[0] = mrow[1] = -1e30f;
    lrow[0] = lrow[1] = 0.f;
#pragma unroll
    for (int nt = 0; nt < 8; nt++)
#pragma unroll
        for (int c = 0; c < 4; c++) O[nt][c] = 0.f;

    const int rq = wid * 16;
    __syncthreads();

    for (int s0 = 0; s0 < SEQLEN; s0 += BS) {
        // ---- load K,V tiles, pre-split to tf32 hi/lo ----
        {
            const int c = tx * 4;
#pragma unroll
            for (int rr = 0; rr < 4; rr++) {
                const int r = ty + rr * 16;
                float4 kv = *(const float4*)(Kg + base + (size_t)(s0 + r) * rowstride + c);
                uint32_t hh, ll;
                split_tf32(kv.x, hh, ll); Khi[r*KSTR + c+0] = __uint_as_float(hh); Klo[r*KSTR + c+0] = __uint_as_float(ll);
                split_tf32(kv.y, hh, ll); Khi[r*KSTR + c+1] = __uint_as_float(hh); Klo[r*KSTR + c+1] = __uint_as_float(ll);
                split_tf32(kv.z, hh, ll); Khi[r*KSTR + c+2] = __uint_as_float(hh); Klo[r*KSTR + c+2] = __uint_as_float(ll);
                split_tf32(kv.w, hh, ll); Khi[r*KSTR + c+3] = __uint_as_float(hh); Klo[r*KSTR + c+3] = __uint_as_float(ll);
                float4 vv = *(const float4*)(Vg + base + (size_t)(s0 + r) * rowstride + c);
                split_tf32(vv.x, hh, ll); Vhi[r*VSTR + c+0] = __uint_as_float(hh); Vlo[r*VSTR + c+0] = __uint_as_float(ll);
                split_tf32(vv.y, hh, ll); Vhi[r*VSTR + c+1] = __uint_as_float(hh); Vlo[r*VSTR + c+1] = __uint_as_float(ll);
                split_tf32(vv.z, hh, ll); Vhi[r*VSTR + c+2] = __uint_as_float(hh); Vlo[r*VSTR + c+2] = __uint_as_float(ll);
                split_tf32(vv.w, hh, ll); Vhi[r*VSTR + c+3] = __uint_as_float(hh); Vlo[r*VSTR + c+3] = __uint_as_float(ll);
            }
        }
        __syncthreads();

        // ---- S = Q @ K^T  (tf32x3) ----
        float S[8][4];
#pragma unroll
        for (int nt = 0; nt < 8; nt++)
#pragma unroll
            for (int c = 0; c < 4; c++) S[nt][c] = 0.f;

#pragma unroll
        for (int ks = 0; ks < 8; ks++) {
            const int kk = ks * 8;
            uint32_t ahi[4], alo[4];
            split_tf32(Qs[(rq + g) * QSTR + kk + t],         ahi[0], alo[0]);
            split_tf32(Qs[(rq + g + 8) * QSTR + kk + t],     ahi[1], alo[1]);
            split_tf32(Qs[(rq + g) * QSTR + kk + t + 4],     ahi[2], alo[2]);
            split_tf32(Qs[(rq + g + 8) * QSTR + kk + t + 4], ahi[3], alo[3]);
            // pass-major across nt: dependent mmas 8 apart
#pragma unroll
            for (int nt = 0; nt < 8; nt++) {
                uint32_t bhi[2];
                bhi[0] = __float_as_uint(Khi[(nt*8 + g) * KSTR + kk + t]);
                bhi[1] = __float_as_uint(Khi[(nt*8 + g) * KSTR + kk + t + 4]);
                mma8(S[nt], ahi, bhi);
            }
#pragma unroll
            for (int nt = 0; nt < 8; nt++) {
                uint32_t bhi[2];
                bhi[0] = __float_as_uint(Khi[(nt*8 + g) * KSTR + kk + t]);
                bhi[1] = __float_as_uint(Khi[(nt*8 + g) * KSTR + kk + t + 4]);
                mma8(S[nt], alo, bhi);
            }
#pragma unroll
            for (int nt = 0; nt < 8; nt++) {
                uint32_t blo[2];
                blo[0] = __float_as_uint(Klo[(nt*8 + g) * KSTR + kk + t]);
                blo[1] = __float_as_uint(Klo[(nt*8 + g) * KSTR + kk + t + 4]);
                mma8(S[nt], ahi, blo);
            }
        }

        // ---- scale + diagonal mask ----
#pragma unroll
        for (int nt = 0; nt < 8; nt++) {
#pragma unroll
            for (int c = 0; c < 4; c++) {
                const int col = s0 + nt * 8 + 2 * t + (c & 1);
                const int row = q0 + rq + g + ((c >= 2) ? 8 : 0);
                float s = S[nt][c] * scale;
                if (col == row) s = -1e30f;
                S[nt][c] = s;
            }
        }

        // ---- online softmax ----
        float mx0 = -1e30f, mx1 = -1e30f;
#pragma unroll
        for (int nt = 0; nt < 8; nt++) {
            mx0 = fmaxf(mx0, fmaxf(S[nt][0], S[nt][1]));
            mx1 = fmaxf(mx1, fmaxf(S[nt][2], S[nt][3]));
        }
        mx0 = fmaxf(mx0, __shfl_xor_sync(0xffffffffu, mx0, 1));
        mx0 = fmaxf(mx0, __shfl_xor_sync(0xffffffffu, mx0, 2));
        mx1 = fmaxf(mx1, __shfl_xor_sync(0xffffffffu, mx1, 1));
        mx1 = fmaxf(mx1, __shfl_xor_sync(0xffffffffu, mx1, 2));

        const float mn0 = fmaxf(mrow[0], mx0);
        const float mn1 = fmaxf(mrow[1], mx1);
        const float corr0 = __expf(mrow[0] - mn0);
        const float corr1 = __expf(mrow[1] - mn1);
        mrow[0] = mn0; mrow[1] = mn1;

        float rs0 = 0.f, rs1 = 0.f;
#pragma unroll
        for (int nt = 0; nt < 8; nt++) {
            float p0 = __expf(S[nt][0] - mn0);
            float p1 = __expf(S[nt][1] - mn0);
            float p2 = __expf(S[nt][2] - mn1);
            float p3 = __expf(S[nt][3] - mn1);
            S[nt][0] = p0; S[nt][1] = p1; S[nt][2] = p2; S[nt][3] = p3;
            rs0 += p0 + p1;
            rs1 += p2 + p3;
        }
        rs0 += __shfl_xor_sync(0xffffffffu, rs0, 1);
        rs0 += __shfl_xor_sync(0xffffffffu, rs0, 2);
        rs1 += __shfl_xor_sync(0xffffffffu, rs1, 1);
        rs1 += __shfl_xor_sync(0xffffffffu, rs1, 2);

        lrow[0] = lrow[0] * corr0 + rs0;
        lrow[1] = lrow[1] * corr1 + rs1;
#pragma unroll
        for (int nt = 0; nt < 8; nt++) {
            O[nt][0] *= corr0; O[nt][1] *= corr0;
            O[nt][2] *= corr1; O[nt][3] *= corr1;
        }

        // ---- O += P @ V : P fragments via intra-quad shuffles (no SMEM) ----
#pragma unroll
        for (int ks = 0; ks < 8; ks++) {
            const int kk = ks * 8;
            const int srcA = (lane & ~3) | (t >> 1);
            const int srcB = srcA | 2;
            float p00 = __shfl_sync(0xffffffffu, S[ks][0], srcA);
            float p01 = __shfl_sync(0xffffffffu, S[ks][1], srcA);
            float p02 = __shfl_sync(0xffffffffu, S[ks][2], srcA);
            float p03 = __shfl_sync(0xffffffffu, S[ks][3], srcA);
            float p10 = __shfl_sync(0xffffffffu, S[ks][0], srcB);
            float p11 = __shfl_sync(0xffffffffu, S[ks][1], srcB);
            float p12 = __shfl_sync(0xffffffffu, S[ks][2], srcB);
            float p13 = __shfl_sync(0xffffffffu, S[ks][3], srcB);
            const bool odd = (t & 1);
            float a0 = odd ? p01 : p00;   // P[g   ][kk+t]
            float a1 = odd ? p03 : p02;   // P[g+8 ][kk+t]
            float a2 = odd ? p11 : p10;   // P[g   ][kk+t+4]
            float a3 = odd ? p13 : p12;   // P[g+8 ][kk+t+4]
            uint32_t ahi[4], alo[4];
            split_tf32(a0, ahi[0], alo[0]);
            split_tf32(a1, ahi[1], alo[1]);
            split_tf32(a2, ahi[2], alo[2]);
            split_tf32(a3, ahi[3], alo[3]);
#pragma unroll
            for (int nt = 0; nt < 8; nt++) {
                uint32_t bhi[2];
                bhi[0] = __float_as_uint(Vhi[(kk + t) * VSTR + nt*8 + g]);
                bhi[1] = __float_as_uint(Vhi[(kk + t + 4) * VSTR + nt*8 + g]);
                mma8(O[nt], ahi, bhi);
            }
#pragma unroll
            for (int nt = 0; nt < 8; nt++) {
                uint32_t bhi[2];
                bhi[0] = __float_as_uint(Vhi[(kk + t) * VSTR + nt*8 + g]);
                bhi[1] = __float_as_uint(Vhi[(kk + t + 4) * VSTR + nt*8 + g]);
                mma8(O[nt], alo, bhi);
            }
#pragma unroll
            for (int nt = 0; nt < 8; nt++) {
                uint32_t blo[2];
                blo[0] = __float_as_uint(Vlo[(kk + t) * VSTR + nt*8 + g]);
                blo[1] = __float_as_uint(Vlo[(kk + t + 4) * VSTR + nt*8 + g]);
                mma8(O[nt], ahi, blo);
            }
        }
        __syncthreads();   // before next tile overwrites K/V
    }

    // ---- finalize ----
    const float inv0 = 1.f / lrow[0];
    const float inv1 = 1.f / lrow[1];
#pragma unroll
    for (int nt = 0; nt < 8; nt++) {
        const int row = q0 + rq + g;
        const int col = nt * 8 + 2 * t;
        *(float2*)(Og + base + (size_t)row * rowstride + col) =
            make_float2(O[nt][0] * inv0, O[nt][1] * inv0);
        *(float2*)(Og + base + (size_t)(row + 8) * rowstride + col) =
            make_float2(O[nt][2] * inv1, O[nt][3] * inv1);
    }
}

// ---------------- launch ------------------------------------------------------
extern "C" void kernel_launch(void* const* d_in, const int* in_sizes, int n_in,
                              void* d_out, int out_size)
{
    (void)in_sizes; (void)n_in; (void)out_size;
    const float* x  = (const float*)d_in[0];
    const float* wq = (const float*)d_in[1];
    const float* wk = (const float*)d_in[2];
    const float* wv = (const float*)d_in[3];
    const float* wo = (const float*)d_in[4];
    float* out = (float*)d_out;

    float *qp, *kp, *vp, *ap;
    cudaGetSymbolAddress((void**)&qp, g_q);
    cudaGetSymbolAddress((void**)&kp, g_k);
    cudaGetSymbolAddress((void**)&vp, g_v);
    cudaGetSymbolAddress((void**)&ap, g_a);

    cudaFuncSetAttribute(gemm_nt, cudaFuncAttributeMaxDynamicSharedMemorySize, GEMM_SMEM_BYTES);
    cudaFuncSetAttribute(attn_kernel, cudaFuncAttributeMaxDynamicSharedMemorySize, ATTN_SMEM_BYTES);

    // 1) QKV projections (fused via grid.z)
    {
        dim3 grid(DIM / GBN, MTOT / GBM, 3);
        gemm_nt<<<grid, 256, GEMM_SMEM_BYTES>>>(x, wq, wk, wv, qp, kp, vp);
    }
    // 2) attention
    {
        dim3 grid(SEQLEN / BQ, BATCH * NHEADS);
        attn_kernel<<<grid, 256, ATTN_SMEM_BYTES>>>(qp, kp, vp, ap);
    }
    // 3) output projection
    {
        dim3 grid(DIM / GBN, MTOT / GBM, 1);
        gemm_nt<<<grid, 256, GEMM_SMEM_BYTES>>>(ap, wo, wo, wo, out, out, out);
    }
}

// round 6
// speedup vs baseline: 2.5601x; 1.6607x over previous
#include <cuda_runtime.h>
#include <cuda_bf16.h>
#include <math.h>
#include <stdint.h>

#define BATCH   4
#define SEQLEN  2048
#define NHEADS  16
#define HDIM    64
#define DIM     1024
#define MTOT    (BATCH * SEQLEN)   // 8192

// ---------------- scratch (static __device__, no allocs allowed) -------------
__device__ float g_q[MTOT * DIM];
__device__ float g_k[MTOT * DIM];
__device__ float g_v[MTOT * DIM];
__device__ float g_a[MTOT * DIM];

// ---------------- bf16x2 helpers ---------------------------------------------
// pack2(lo, hi): bf16x2 word, 'lo' in low 16 bits. PTX cvt packs first src high.
__device__ __forceinline__ uint32_t pack2(float lo, float hi) {
    uint32_t r;
    asm("cvt.rn.bf16x2.f32 %0, %1, %2;" : "=r"(r) : "f"(hi), "f"(lo));
    return r;
}
// 2-way bf16 split of two floats, packed: h = (bh(x0), bh(x1)), l = residuals
__device__ __forceinline__ void splitpack(float x0, float x1, uint32_t& h, uint32_t& l) {
    h = pack2(x0, x1);
    float h0 = __uint_as_float(h << 16);
    float h1 = __uint_as_float(h & 0xffff0000u);
    l = pack2(x0 - h0, x1 - h1);
}
// D += A*B, one m16n8k16 bf16 tile, fp32 accumulate
__device__ __forceinline__ void mma16(float* d, const uint32_t* a, const uint32_t* b) {
    asm volatile(
        "mma.sync.aligned.m16n8k16.row.col.f32.bf16.bf16.f32 "
        "{%0,%1,%2,%3}, {%4,%5,%6,%7}, {%8,%9}, {%0,%1,%2,%3};"
        : "+f"(d[0]), "+f"(d[1]), "+f"(d[2]), "+f"(d[3])
        : "r"(a[0]), "r"(a[1]), "r"(a[2]), "r"(a[3]), "r"(b[0]), "r"(b[1]));
}
// split+pack 8 consecutive k-floats (two float4) -> 4 hi words + 4 lo words
__device__ __forceinline__ void pack_store8(uint32_t* hi, uint32_t* lo, int widx,
                                            float4 a, float4 b) {
    uint32_t h0,l0,h1,l1,h2,l2,h3,l3;
    splitpack(a.x, a.y, h0, l0);
    splitpack(a.z, a.w, h1, l1);
    splitpack(b.x, b.y, h2, l2);
    splitpack(b.z, b.w, h3, l3);
    *(uint4*)(hi + widx) = make_uint4(h0, h1, h2, h3);
    *(uint4*)(lo + widx) = make_uint4(l0, l1, l2, l3);
}

// ---------------- GEMM: C[m][n] = sum_k A[m][k] * B[n][k]  (NT) --------------
// CTA 128x128x32, 8 warps of 64x32, bf16x2 3-pass m16n8k16, double-buffered.
#define GBM 128
#define GBN 128
#define GBK 32
#define RSTR 20                         // words/row: 16 kwords + 4 pad (20g+t: all banks)
#define GARR (GBM * RSTR)               // 2560 words per array
#define GSS  (4 * GARR)                 // Ahi,Alo,Bhi,Blo per stage
#define GEMM_SMEM_BYTES (2 * GSS * 4)   // 81920

__global__ void __launch_bounds__(256, 2)
gemm_nt(const float* __restrict__ A,
        const float* __restrict__ B0, const float* __restrict__ B1, const float* __restrict__ B2,
        float* __restrict__ C0, float* __restrict__ C1, float* __restrict__ C2)
{
    const float* __restrict__ B = (blockIdx.z == 0) ? B0 : (blockIdx.z == 1 ? B1 : B2);
    float* __restrict__ C       = (blockIdx.z == 0) ? C0 : (blockIdx.z == 1 ? C1 : C2);

    extern __shared__ uint32_t gsm[];
    const int K = DIM;
    const int N = DIM;

    const int tid  = threadIdx.x;
    const int lane = tid & 31;
    const int wid  = tid >> 5;
    const int g    = lane >> 2;
    const int t    = lane & 3;
    const int wm   = wid >> 2;
    const int wn   = wid & 3;
    const int m0   = blockIdx.y * GBM;
    const int n0   = blockIdx.x * GBN;

    const int lr  = tid >> 2;            // 0..63
    const int lc  = (tid & 3) * 8;       // k float offset 0,8,16,24
    const int kw0 = (tid & 3) * 4;       // kword offset

    const float* Ag0 = A + (size_t)(m0 + lr) * K + lc;
    const float* Ag1 = A + (size_t)(m0 + lr + 64) * K + lc;
    const float* Bg0 = B + (size_t)(n0 + lr) * K + lc;
    const float* Bg1 = B + (size_t)(n0 + lr + 64) * K + lc;

    float acc[4][4][4];
#pragma unroll
    for (int i = 0; i < 4; i++)
#pragma unroll
        for (int j = 0; j < 4; j++)
#pragma unroll
            for (int c = 0; c < 4; c++) acc[i][j][c] = 0.f;

    const int NT = K / GBK;

    // prologue: stage 0
    {
        uint32_t* Ahi = gsm;
        uint32_t* Alo = gsm + GARR;
        uint32_t* Bhi = gsm + 2 * GARR;
        uint32_t* Blo = gsm + 3 * GARR;
        pack_store8(Ahi, Alo, lr * RSTR + kw0,        *(const float4*)Ag0, *(const float4*)(Ag0 + 4));
        pack_store8(Ahi, Alo, (lr + 64) * RSTR + kw0, *(const float4*)Ag1, *(const float4*)(Ag1 + 4));
        pack_store8(Bhi, Blo, lr * RSTR + kw0,        *(const float4*)Bg0, *(const float4*)(Bg0 + 4));
        pack_store8(Bhi, Blo, (lr + 64) * RSTR + kw0, *(const float4*)Bg1, *(const float4*)(Bg1 + 4));
    }
    __syncthreads();

    for (int kt = 0; kt < NT; kt++) {
        const int cur = kt & 1;
        const bool has = (kt + 1 < NT);
        float4 va0a, va0b, va1a, va1b, vb0a, vb0b, vb1a, vb1b;
        if (has) {
            const int ko = (kt + 1) * GBK;
            va0a = *(const float4*)(Ag0 + ko); va0b = *(const float4*)(Ag0 + ko + 4);
            va1a = *(const float4*)(Ag1 + ko); va1b = *(const float4*)(Ag1 + ko + 4);
            vb0a = *(const float4*)(Bg0 + ko); vb0b = *(const float4*)(Bg0 + ko + 4);
            vb1a = *(const float4*)(Bg1 + ko); vb1b = *(const float4*)(Bg1 + ko + 4);
        }

        const uint32_t* Ahi = gsm + cur * GSS;
        const uint32_t* Alo = Ahi + GARR;
        const uint32_t* Bhi = Ahi + 2 * GARR;
        const uint32_t* Blo = Ahi + 3 * GARR;

#pragma unroll
        for (int ck = 0; ck < 2; ck++) {         // two k16 chunks per 32-k tile
            const int kwb = ck * 8;
            uint32_t ahi[4][4], alo[4][4];
#pragma unroll
            for (int mi = 0; mi < 4; mi++) {
                const int rb = wm * 64 + mi * 16 + g;
                ahi[mi][0] = Ahi[rb * RSTR + kwb + t];
                ahi[mi][1] = Ahi[(rb + 8) * RSTR + kwb + t];
                ahi[mi][2] = Ahi[rb * RSTR + kwb + t + 4];
                ahi[mi][3] = Ahi[(rb + 8) * RSTR + kwb + t + 4];
                alo[mi][0] = Alo[rb * RSTR + kwb + t];
                alo[mi][1] = Alo[(rb + 8) * RSTR + kwb + t];
                alo[mi][2] = Alo[rb * RSTR + kwb + t + 4];
                alo[mi][3] = Alo[(rb + 8) * RSTR + kwb + t + 4];
            }
#pragma unroll
            for (int nj = 0; nj < 4; nj++) {
                const int cb = wn * 32 + nj * 8 + g;
                uint32_t bhi[2], blo[2];
                bhi[0] = Bhi[cb * RSTR + kwb + t];
                bhi[1] = Bhi[cb * RSTR + kwb + t + 4];
                blo[0] = Blo[cb * RSTR + kwb + t];
                blo[1] = Blo[cb * RSTR + kwb + t + 4];
#pragma unroll
                for (int mi = 0; mi < 4; mi++) mma16(acc[mi][nj], ahi[mi], bhi);
#pragma unroll
                for (int mi = 0; mi < 4; mi++) mma16(acc[mi][nj], alo[mi], bhi);
#pragma unroll
                for (int mi = 0; mi < 4; mi++) mma16(acc[mi][nj], ahi[mi], blo);
            }
        }

        if (has) {
            uint32_t* nAhi = gsm + (cur ^ 1) * GSS;
            uint32_t* nAlo = nAhi + GARR;
            uint32_t* nBhi = nAhi + 2 * GARR;
            uint32_t* nBlo = nAhi + 3 * GARR;
            pack_store8(nAhi, nAlo, lr * RSTR + kw0,        va0a, va0b);
            pack_store8(nAhi, nAlo, (lr + 64) * RSTR + kw0, va1a, va1b);
            pack_store8(nBhi, nBlo, lr * RSTR + kw0,        vb0a, vb0b);
            pack_store8(nBhi, nBlo, (lr + 64) * RSTR + kw0, vb1a, vb1b);
        }
        __syncthreads();
    }

#pragma unroll
    for (int mi = 0; mi < 4; mi++) {
#pragma unroll
        for (int nj = 0; nj < 4; nj++) {
            const int row = m0 + wm * 64 + mi * 16 + g;
            const int col = n0 + wn * 32 + nj * 8 + 2 * t;
            *(float2*)(C + (size_t)row * N + col)       = make_float2(acc[mi][nj][0], acc[mi][nj][1]);
            *(float2*)(C + (size_t)(row + 8) * N + col) = make_float2(acc[mi][nj][2], acc[mi][nj][3]);
        }
    }
}

// ---------------- Flash attention (bf16x2 3-pass mma) with diagonal mask -----
// Grid: (L/BQ, B*H). 8 warps; warp w owns query rows [w*16, w*16+16).
#define BQ 128
#define BS 64
#define QS 36   // words/row: 32 kwords + 4 pad (bank 4g+t distinct)
#define KS 36
#define VS 72   // words/sword-row: 64 d + 8 pad (bank 8t+g distinct)
#define ATTN_SMEM_WORDS (2 * BQ * QS + 2 * BS * KS + 2 * 32 * VS)
#define ATTN_SMEM_BYTES (ATTN_SMEM_WORDS * 4)   // 73728

__global__ void __launch_bounds__(256, 2)
attn_kernel(const float* __restrict__ Qg, const float* __restrict__ Kg,
            const float* __restrict__ Vg, float* __restrict__ Og)
{
    extern __shared__ uint32_t smw[];
    uint32_t* Qhi = smw;                    // [128][QS]
    uint32_t* Qlo = Qhi + BQ * QS;
    uint32_t* Khi = Qlo + BQ * QS;          // [64][KS]
    uint32_t* Klo = Khi + BS * KS;
    uint32_t* Vhi = Klo + BS * KS;          // [32 swords][VS]
    uint32_t* Vlo = Vhi + 32 * VS;

    const int tid  = threadIdx.x;
    const int lane = tid & 31;
    const int wid  = tid >> 5;
    const int g    = lane >> 2;
    const int t    = lane & 3;
    const int tx   = tid & 15;
    const int ty   = tid >> 4;
    const int q0   = blockIdx.x * BQ;
    const int bh   = blockIdx.y;
    const int b    = bh >> 4;
    const int h    = bh & 15;
    const float scale = 0.125f;

    const size_t rowstride = (size_t)NHEADS * HDIM;  // 1024
    const size_t base = ((size_t)b * SEQLEN) * rowstride + (size_t)h * HDIM;

    // ---- load + split Q tile [BQ][64] once ----
    {
        const int c = tx * 4;
#pragma unroll
        for (int rr = 0; rr < 8; rr++) {
            const int r = ty + rr * 16;
            float4 v = *(const float4*)(Qg + base + (size_t)(q0 + r) * rowstride + c);
            uint32_t h0, l0, h1, l1;
            splitpack(v.x, v.y, h0, l0);
            splitpack(v.z, v.w, h1, l1);
            *(uint2*)&Qhi[r * QS + tx * 2] = make_uint2(h0, h1);
            *(uint2*)&Qlo[r * QS + tx * 2] = make_uint2(l0, l1);
        }
    }

    float mrow[2], lrow[2], O[8][4];
    mrow[0] = mrow[1] = -1e30f;
    lrow[0] = lrow[1] = 0.f;
#pragma unroll
    for (int nt = 0; nt < 8; nt++)
#pragma unroll
        for (int c = 0; c < 4; c++) O[nt][c] = 0.f;

    const int rq = wid * 16;
    __syncthreads();

    for (int s0 = 0; s0 < SEQLEN; s0 += BS) {
        // ---- K tile: [64 s][32 kwords], packed over d ----
        {
            const int r = tid >> 2;          // s row 0..63
            const int c = (tid & 3) * 16;    // d offset
            const float* kr = Kg + base + (size_t)(s0 + r) * rowstride + c;
            pack_store8(Khi, Klo, r * KS + (tid & 3) * 8,
                        *(const float4*)kr, *(const float4*)(kr + 4));
            pack_store8(Khi, Klo, r * KS + (tid & 3) * 8 + 4,
                        *(const float4*)(kr + 8), *(const float4*)(kr + 12));
        }
        // ---- V tile: [32 swords][64 d], packed over s pairs ----
        {
            const int s2 = tid >> 3;         // sword 0..31
            const int db = (tid & 7) * 8;    // d offset
            const float* v0 = Vg + base + (size_t)(s0 + 2 * s2) * rowstride + db;
            const float* v1 = v0 + rowstride;
            float4 a0 = *(const float4*)v0, a1 = *(const float4*)(v0 + 4);
            float4 b0 = *(const float4*)v1, b1 = *(const float4*)(v1 + 4);
            uint32_t hw[8], lw[8];
            splitpack(a0.x, b0.x, hw[0], lw[0]);
            splitpack(a0.y, b0.y, hw[1], lw[1]);
            splitpack(a0.z, b0.z, hw[2], lw[2]);
            splitpack(a0.w, b0.w, hw[3], lw[3]);
            splitpack(a1.x, b1.x, hw[4], lw[4]);
            splitpack(a1.y, b1.y, hw[5], lw[5]);
            splitpack(a1.z, b1.z, hw[6], lw[6]);
            splitpack(a1.w, b1.w, hw[7], lw[7]);
            *(uint4*)&Vhi[s2 * VS + db]     = make_uint4(hw[0], hw[1], hw[2], hw[3]);
            *(uint4*)&Vhi[s2 * VS + db + 4] = make_uint4(hw[4], hw[5], hw[6], hw[7]);
            *(uint4*)&Vlo[s2 * VS + db]     = make_uint4(lw[0], lw[1], lw[2], lw[3]);
            *(uint4*)&Vlo[s2 * VS + db + 4] = make_uint4(lw[4], lw[5], lw[6], lw[7]);
        }
        __syncthreads();

        // ---- S = Q @ K^T  (4 k16 chunks over d=64) ----
        float S[8][4];
#pragma unroll
        for (int nt = 0; nt < 8; nt++)
#pragma unroll
            for (int c = 0; c < 4; c++) S[nt][c] = 0.f;

#pragma unroll
        for (int ks = 0; ks < 4; ks++) {
            const int kwb = ks * 8;
            uint32_t ahi[4], alo[4];
            ahi[0] = Qhi[(rq + g) * QS + kwb + t];
            ahi[1] = Qhi[(rq + g + 8) * QS + kwb + t];
            ahi[2] = Qhi[(rq + g) * QS + kwb + t + 4];
            ahi[3] = Qhi[(rq + g + 8) * QS + kwb + t + 4];
            alo[0] = Qlo[(rq + g) * QS + kwb + t];
            alo[1] = Qlo[(rq + g + 8) * QS + kwb + t];
            alo[2] = Qlo[(rq + g) * QS + kwb + t + 4];
            alo[3] = Qlo[(rq + g + 8) * QS + kwb + t + 4];
#pragma unroll
            for (int nt = 0; nt < 8; nt++) {
                uint32_t bhi[2];
                bhi[0] = Khi[(nt * 8 + g) * KS + kwb + t];
                bhi[1] = Khi[(nt * 8 + g) * KS + kwb + t + 4];
                mma16(S[nt], ahi, bhi);
            }
#pragma unroll
            for (int nt = 0; nt < 8; nt++) {
                uint32_t bhi[2];
                bhi[0] = Khi[(nt * 8 + g) * KS + kwb + t];
                bhi[1] = Khi[(nt * 8 + g) * KS + kwb + t + 4];
                mma16(S[nt], alo, bhi);
            }
#pragma unroll
            for (int nt = 0; nt < 8; nt++) {
                uint32_t blo[2];
                blo[0] = Klo[(nt * 8 + g) * KS + kwb + t];
                blo[1] = Klo[(nt * 8 + g) * KS + kwb + t + 4];
                mma16(S[nt], ahi, blo);
            }
        }

        // ---- scale + diagonal mask ----
#pragma unroll
        for (int nt = 0; nt < 8; nt++) {
#pragma unroll
            for (int c = 0; c < 4; c++) {
                const int col = s0 + nt * 8 + 2 * t + (c & 1);
                const int row = q0 + rq + g + ((c >= 2) ? 8 : 0);
                float s = S[nt][c] * scale;
                if (col == row) s = -1e30f;
                S[nt][c] = s;
            }
        }

        // ---- online softmax ----
        float mx0 = -1e30f, mx1 = -1e30f;
#pragma unroll
        for (int nt = 0; nt < 8; nt++) {
            mx0 = fmaxf(mx0, fmaxf(S[nt][0], S[nt][1]));
            mx1 = fmaxf(mx1, fmaxf(S[nt][2], S[nt][3]));
        }
        mx0 = fmaxf(mx0, __shfl_xor_sync(0xffffffffu, mx0, 1));
        mx0 = fmaxf(mx0, __shfl_xor_sync(0xffffffffu, mx0, 2));
        mx1 = fmaxf(mx1, __shfl_xor_sync(0xffffffffu, mx1, 1));
        mx1 = fmaxf(mx1, __shfl_xor_sync(0xffffffffu, mx1, 2));

        const float mn0 = fmaxf(mrow[0], mx0);
        const float mn1 = fmaxf(mrow[1], mx1);
        const float corr0 = __expf(mrow[0] - mn0);
        const float corr1 = __expf(mrow[1] - mn1);
        mrow[0] = mn0; mrow[1] = mn1;

        float rs0 = 0.f, rs1 = 0.f;
#pragma unroll
        for (int nt = 0; nt < 8; nt++) {
            float p0 = __expf(S[nt][0] - mn0);
            float p1 = __expf(S[nt][1] - mn0);
            float p2 = __expf(S[nt][2] - mn1);
            float p3 = __expf(S[nt][3] - mn1);
            S[nt][0] = p0; S[nt][1] = p1; S[nt][2] = p2; S[nt][3] = p3;
            rs0 += p0 + p1;
            rs1 += p2 + p3;
        }
        rs0 += __shfl_xor_sync(0xffffffffu, rs0, 1);
        rs0 += __shfl_xor_sync(0xffffffffu, rs0, 2);
        rs1 += __shfl_xor_sync(0xffffffffu, rs1, 1);
        rs1 += __shfl_xor_sync(0xffffffffu, rs1, 2);

        lrow[0] = lrow[0] * corr0 + rs0;
        lrow[1] = lrow[1] * corr1 + rs1;
#pragma unroll
        for (int nt = 0; nt < 8; nt++) {
            O[nt][0] *= corr0; O[nt][1] *= corr0;
            O[nt][2] *= corr1; O[nt][3] *= corr1;
        }

        // ---- O += P @ V : C-frag of QK IS the A-frag of PV (k16) ----
#pragma unroll
        for (int ks = 0; ks < 4; ks++) {
            uint32_t phi[4], plo[4];
            splitpack(S[2 * ks][0],     S[2 * ks][1],     phi[0], plo[0]);   // (g,   2t..)
            splitpack(S[2 * ks][2],     S[2 * ks][3],     phi[1], plo[1]);   // (g+8, 2t..)
            splitpack(S[2 * ks + 1][0], S[2 * ks + 1][1], phi[2], plo[2]);   // (g,   2t+8..)
            splitpack(S[2 * ks + 1][2], S[2 * ks + 1][3], phi[3], plo[3]);   // (g+8, 2t+8..)
            const int swb = ks * 8;
#pragma unroll
            for (int nt = 0; nt < 8; nt++) {
                uint32_t bhi[2];
                bhi[0] = Vhi[(swb + t) * VS + nt * 8 + g];
                bhi[1] = Vhi[(swb + t + 4) * VS + nt * 8 + g];
                mma16(O[nt], phi, bhi);
            }
#pragma unroll
            for (int nt = 0; nt < 8; nt++) {
                uint32_t bhi[2];
                bhi[0] = Vhi[(swb + t) * VS + nt * 8 + g];
                bhi[1] = Vhi[(swb + t + 4) * VS + nt * 8 + g];
                mma16(O[nt], plo, bhi);
            }
#pragma unroll
            for (int nt = 0; nt < 8; nt++) {
                uint32_t blo[2];
                blo[0] = Vlo[(swb + t) * VS + nt * 8 + g];
                blo[1] = Vlo[(swb + t + 4) * VS + nt * 8 + g];
                mma16(O[nt], phi, blo);
            }
        }
        __syncthreads();   // before next tile overwrites K/V
    }

    // ---- finalize ----
    const float inv0 = 1.f / lrow[0];
    const float inv1 = 1.f / lrow[1];
#pragma unroll
    for (int nt = 0; nt < 8; nt++) {
        const int row = q0 + rq + g;
        const int col = nt * 8 + 2 * t;
        *(float2*)(Og + base + (size_t)row * rowstride + col) =
            make_float2(O[nt][0] * inv0, O[nt][1] * inv0);
        *(float2*)(Og + base + (size_t)(row + 8) * rowstride + col) =
            make_float2(O[nt][2] * inv1, O[nt][3] * inv1);
    }
}

// ---------------- launch ------------------------------------------------------
extern "C" void kernel_launch(void* const* d_in, const int* in_sizes, int n_in,
                              void* d_out, int out_size)
{
    (void)in_sizes; (void)n_in; (void)out_size;
    const float* x  = (const float*)d_in[0];
    const float* wq = (const float*)d_in[1];
    const float* wk = (const float*)d_in[2];
    const float* wv = (const float*)d_in[3];
    const float* wo = (const float*)d_in[4];
    float* out = (float*)d_out;

    float *qp, *kp, *vp, *ap;
    cudaGetSymbolAddress((void**)&qp, g_q);
    cudaGetSymbolAddress((void**)&kp, g_k);
    cudaGetSymbolAddress((void**)&vp, g_v);
    cudaGetSymbolAddress((void**)&ap, g_a);

    cudaFuncSetAttribute(gemm_nt, cudaFuncAttributeMaxDynamicSharedMemorySize, GEMM_SMEM_BYTES);
    cudaFuncSetAttribute(attn_kernel, cudaFuncAttributeMaxDynamicSharedMemorySize, ATTN_SMEM_BYTES);

    // 1) QKV projections (fused via grid.z)
    {
        dim3 grid(DIM / GBN, MTOT / GBM, 3);
        gemm_nt<<<grid, 256, GEMM_SMEM_BYTES>>>(x, wq, wk, wv, qp, kp, vp);
    }
    // 2) attention
    {
        dim3 grid(SEQLEN / BQ, BATCH * NHEADS);
        attn_kernel<<<grid, 256, ATTN_SMEM_BYTES>>>(qp, kp, vp, ap);
    }
    // 3) output projection
    {
        dim3 grid(DIM / GBN, MTOT / GBM, 1);
        gemm_nt<<<grid, 256, GEMM_SMEM_BYTES>>>(ap, wo, wo, wo, out, out, out);
    }
}

// round 9
// speedup vs baseline: 3.7350x; 1.4590x over previous
#include <cuda_runtime.h>
#include <cuda_fp16.h>
#include <math.h>
#include <stdint.h>

#define BATCH   4
#define SEQLEN  2048
#define NHEADS  16
#define HDIM    64
#define DIM     1024
#define MTOT    (BATCH * SEQLEN)   // 8192
#define KW      (DIM / 2)          // 512 packed words per row

// ---------------- scratch (static __device__, no allocs allowed) -------------
__device__ float g_q[MTOT * DIM];
__device__ float g_k[MTOT * DIM];
__device__ float g_v[MTOT * DIM];
__device__ float g_a[MTOT * DIM];
// packed fp16 operands (word = 2 fp16, element 2w in low half)
__device__ uint32_t g_xh[MTOT * KW];              // x  (A-side: hi only)
__device__ uint32_t g_ah[MTOT * KW];              // attn out (A-side: hi only)
__device__ uint32_t g_wqh[DIM * KW], g_wql[DIM * KW];
__device__ uint32_t g_wkh[DIM * KW], g_wkl[DIM * KW];
__device__ uint32_t g_wvh[DIM * KW], g_wvl[DIM * KW];
__device__ uint32_t g_woh[DIM * KW], g_wol[DIM * KW];

// ---------------- fp16x2 helpers ---------------------------------------------
// pack2h(lo, hi): fp16x2 word, 'lo' in low 16 bits
__device__ __forceinline__ uint32_t pack2h(float lo, float hi) {
    uint32_t r;
    asm("cvt.rn.f16x2.f32 %0, %1, %2;" : "=r"(r) : "f"(hi), "f"(lo));
    return r;
}
__device__ __forceinline__ void unpack2h(uint32_t w, float& lo, float& hi) {
    asm("{.reg .f16 l, h; mov.b32 {l, h}, %2; cvt.f32.f16 %0, l; cvt.f32.f16 %1, h;}"
        : "=f"(lo), "=f"(hi) : "r"(w));
}
__device__ __forceinline__ void splitpackh(float x0, float x1, uint32_t& h, uint32_t& l) {
    h = pack2h(x0, x1);
    float h0, h1;
    unpack2h(h, h0, h1);
    l = pack2h(x0 - h0, x1 - h1);
}
// D += A*B, one m16n8k16 fp16 tile, fp32 accumulate
__device__ __forceinline__ void mma16h(float* d, const uint32_t* a, const uint32_t* b) {
    asm volatile(
        "mma.sync.aligned.m16n8k16.row.col.f32.f16.f16.f32 "
        "{%0,%1,%2,%3}, {%4,%5,%6,%7}, {%8,%9}, {%0,%1,%2,%3};"
        : "+f"(d[0]), "+f"(d[1]), "+f"(d[2]), "+f"(d[3])
        : "r"(a[0]), "r"(a[1]), "r"(a[2]), "r"(a[3]), "r"(b[0]), "r"(b[1]));
}
// pack 8 consecutive floats -> 4 hi words (hi-only path)
__device__ __forceinline__ void pack_store8_hi(uint32_t* hi, int widx, float4 a, float4 b) {
    *(uint4*)(hi + widx) = make_uint4(pack2h(a.x, a.y), pack2h(a.z, a.w),
                                      pack2h(b.x, b.y), pack2h(b.z, b.w));
}

// ---------------- prepack kernels --------------------------------------------
__global__ void prepack_hi(const float* __restrict__ src, uint32_t* __restrict__ hi, int nwords)
{
    int i = blockIdx.x * blockDim.x + threadIdx.x;
    int stride = gridDim.x * blockDim.x;
    for (; i < nwords; i += stride) {
        float2 v = ((const float2*)src)[i];
        hi[i] = pack2h(v.x, v.y);
    }
}
__global__ void prepack_hilo(const float* __restrict__ src, uint32_t* __restrict__ hi,
                             uint32_t* __restrict__ lo, int nwords)
{
    int i = blockIdx.x * blockDim.x + threadIdx.x;
    int stride = gridDim.x * blockDim.x;
    for (; i < nwords; i += stride) {
        float2 v = ((const float2*)src)[i];
        uint32_t h, l;
        splitpackh(v.x, v.y, h, l);
        hi[i] = h;
        lo[i] = l;
    }
}

// ---------------- GEMM: C[m][n] = sum_k A[m][k]*B[n][k]  (NT) ----------------
// CTA 128x128x32, 8 warps of 64x32. fp16 2-pass: A unsplit, B split hi/lo.
// Double-buffered SMEM of prepacked words.
#define RSTR 20                          // words/row: 16 kwords + 4 pad
#define GARR (128 * RSTR)                // 2560 words per array
#define GSS  (3 * GARR)                  // Ah, Bh, Bl per stage
#define GEMM_SMEM_BYTES (2 * GSS * 4)    // 61440

__global__ void __launch_bounds__(256, 2)
gemm_h(const uint32_t* __restrict__ Ahg,
       const uint32_t* __restrict__ Bh0, const uint32_t* __restrict__ Bl0,
       const uint32_t* __restrict__ Bh1, const uint32_t* __restrict__ Bl1,
       const uint32_t* __restrict__ Bh2, const uint32_t* __restrict__ Bl2,
       float* __restrict__ C0, float* __restrict__ C1, float* __restrict__ C2)
{
    const uint32_t* Bhg = (blockIdx.z == 0) ? Bh0 : (blockIdx.z == 1 ? Bh1 : Bh2);
    const uint32_t* Blg = (blockIdx.z == 0) ? Bl0 : (blockIdx.z == 1 ? Bl1 : Bl2);
    float* C            = (blockIdx.z == 0) ? C0 : (blockIdx.z == 1 ? C1 : C2);

    extern __shared__ uint32_t gsm[];
    const int tid  = threadIdx.x;
    const int lane = tid & 31;
    const int wid  = tid >> 5;
    const int g    = lane >> 2;
    const int t    = lane & 3;
    const int wm   = wid >> 2;
    const int wn   = wid & 3;
    const size_t m0 = blockIdx.y * 128;
    const size_t n0 = blockIdx.x * 128;

    const int lr  = tid >> 2;            // 0..63
    const int cw4 = (tid & 3) * 4;       // kword offset 0,4,8,12

    const uint32_t* Ag0 = Ahg + (m0 + lr) * KW + cw4;
    const uint32_t* Ag1 = Ahg + (m0 + lr + 64) * KW + cw4;
    const uint32_t* Bh0p = Bhg + (n0 + lr) * KW + cw4;
    const uint32_t* Bh1p = Bhg + (n0 + lr + 64) * KW + cw4;
    const uint32_t* Bl0p = Blg + (n0 + lr) * KW + cw4;
    const uint32_t* Bl1p = Blg + (n0 + lr + 64) * KW + cw4;

    float acc[4][4][4];
#pragma unroll
    for (int i = 0; i < 4; i++)
#pragma unroll
        for (int j = 0; j < 4; j++)
#pragma unroll
            for (int c = 0; c < 4; c++) acc[i][j][c] = 0.f;

    const int NT = DIM / 32;             // 32 k per tile -> 16 kwords
    const int widx0 = lr * RSTR + cw4;
    const int widx1 = (lr + 64) * RSTR + cw4;

    // prologue: stage 0
    {
        uint32_t* Ah = gsm;
        uint32_t* Bh = gsm + GARR;
        uint32_t* Bl = gsm + 2 * GARR;
        *(uint4*)(Ah + widx0) = *(const uint4*)(Ag0);
        *(uint4*)(Ah + widx1) = *(const uint4*)(Ag1);
        *(uint4*)(Bh + widx0) = *(const uint4*)(Bh0p);
        *(uint4*)(Bh + widx1) = *(const uint4*)(Bh1p);
        *(uint4*)(Bl + widx0) = *(const uint4*)(Bl0p);
        *(uint4*)(Bl + widx1) = *(const uint4*)(Bl1p);
    }
    __syncthreads();

    for (int kt = 0; kt < NT; kt++) {
        const int cur = kt & 1;
        const bool has = (kt + 1 < NT);
        uint4 pa0, pa1, pb0, pb1, pc0, pc1;
        if (has) {
            const int ko = (kt + 1) * 16;
            pa0 = *(const uint4*)(Ag0 + ko);
            pa1 = *(const uint4*)(Ag1 + ko);
            pb0 = *(const uint4*)(Bh0p + ko);
            pb1 = *(const uint4*)(Bh1p + ko);
            pc0 = *(const uint4*)(Bl0p + ko);
            pc1 = *(const uint4*)(Bl1p + ko);
        }

        const uint32_t* Ah = gsm + cur * GSS;
        const uint32_t* Bh = Ah + GARR;
        const uint32_t* Bl = Ah + 2 * GARR;

#pragma unroll
        for (int ck = 0; ck < 2; ck++) {
            const int kwb = ck * 8;
            uint32_t a[4][4];
#pragma unroll
            for (int mi = 0; mi < 4; mi++) {
                const int rb = wm * 64 + mi * 16 + g;
                a[mi][0] = Ah[rb * RSTR + kwb + t];
                a[mi][1] = Ah[(rb + 8) * RSTR + kwb + t];
                a[mi][2] = Ah[rb * RSTR + kwb + t + 4];
                a[mi][3] = Ah[(rb + 8) * RSTR + kwb + t + 4];
            }
#pragma unroll
            for (int nj = 0; nj < 4; nj++) {
                const int cb = wn * 32 + nj * 8 + g;
                uint32_t bh[2], bl[2];
                bh[0] = Bh[cb * RSTR + kwb + t];
                bh[1] = Bh[cb * RSTR + kwb + t + 4];
                bl[0] = Bl[cb * RSTR + kwb + t];
                bl[1] = Bl[cb * RSTR + kwb + t + 4];
#pragma unroll
                for (int mi = 0; mi < 4; mi++) mma16h(acc[mi][nj], a[mi], bh);
#pragma unroll
                for (int mi = 0; mi < 4; mi++) mma16h(acc[mi][nj], a[mi], bl);
            }
        }

        if (has) {
            uint32_t* nAh = gsm + (cur ^ 1) * GSS;
            uint32_t* nBh = nAh + GARR;
            uint32_t* nBl = nAh + 2 * GARR;
            *(uint4*)(nAh + widx0) = pa0;
            *(uint4*)(nAh + widx1) = pa1;
            *(uint4*)(nBh + widx0) = pb0;
            *(uint4*)(nBh + widx1) = pb1;
            *(uint4*)(nBl + widx0) = pc0;
            *(uint4*)(nBl + widx1) = pc1;
        }
        __syncthreads();
    }

#pragma unroll
    for (int mi = 0; mi < 4; mi++) {
#pragma unroll
        for (int nj = 0; nj < 4; nj++) {
            const int row = (int)m0 + wm * 64 + mi * 16 + g;
            const int col = (int)n0 + wn * 32 + nj * 8 + 2 * t;
            *(float2*)(C + (size_t)row * DIM + col)       = make_float2(acc[mi][nj][0], acc[mi][nj][1]);
            *(float2*)(C + (size_t)(row + 8) * DIM + col) = make_float2(acc[mi][nj][2], acc[mi][nj][3]);
        }
    }
}

// ---------------- Flash attention (fp16 2-pass mma) with diagonal mask -------
// Grid: (L/BQ, B*H). 8 warps; warp w owns query rows [w*16, w*16+16).
// Q split hi/lo; K,V stored hi-only. B-fragments register-cached across passes.
#define BQ 128
#define BS 64
#define QS 36
#define KS 36
#define VS 72
#define ATTN_SMEM_WORDS (2 * BQ * QS + BS * KS + 32 * VS)
#define ATTN_SMEM_BYTES (ATTN_SMEM_WORDS * 4)   // 55296

__global__ void __launch_bounds__(256, 2)
attn_kernel(const float* __restrict__ Qg, const float* __restrict__ Kg,
            const float* __restrict__ Vg, float* __restrict__ Og)
{
    extern __shared__ uint32_t smw[];
    uint32_t* Qh  = smw;                    // [128][QS]
    uint32_t* Ql  = Qh + BQ * QS;
    uint32_t* Khi = Ql + BQ * QS;           // [64][KS]
    uint32_t* Vhi = Khi + BS * KS;          // [32 swords][VS]

    const int tid  = threadIdx.x;
    const int lane = tid & 31;
    const int wid  = tid >> 5;
    const int g    = lane >> 2;
    const int t    = lane & 3;
    const int tx   = tid & 15;
    const int ty   = tid >> 4;
    const int q0   = blockIdx.x * BQ;
    const int bh_i = blockIdx.y;
    const int b    = bh_i >> 4;
    const int h    = bh_i & 15;
    const float scale = 0.125f;

    const size_t rowstride = (size_t)NHEADS * HDIM;  // 1024
    const size_t base = ((size_t)b * SEQLEN) * rowstride + (size_t)h * HDIM;

    // ---- load + split Q tile [BQ][64] once ----
    {
        const int c = tx * 4;
#pragma unroll
        for (int rr = 0; rr < 8; rr++) {
            const int r = ty + rr * 16;
            float4 v = *(const float4*)(Qg + base + (size_t)(q0 + r) * rowstride + c);
            uint32_t h0, l0, h1, l1;
            splitpackh(v.x, v.y, h0, l0);
            splitpackh(v.z, v.w, h1, l1);
            *(uint2*)&Qh[r * QS + tx * 2] = make_uint2(h0, h1);
            *(uint2*)&Ql[r * QS + tx * 2] = make_uint2(l0, l1);
        }
    }

    float mrow[2], lrow[2], O[8][4];
    mrow[0] = mrow[1] = -1e30f;
    lrow[0] = lrow[1] = 0.f;
#pragma unroll
    for (int nt = 0; nt < 8; nt++)
#pragma unroll
        for (int c = 0; c < 4; c++) O[nt][c] = 0.f;

    const int rq = wid * 16;
    __syncthreads();

    for (int s0 = 0; s0 < SEQLEN; s0 += BS) {
        // ---- K tile: [64 s][32 kwords] hi only ----
        {
            const int r = tid >> 2;
            const int c = (tid & 3) * 16;
            const float* kr = Kg + base + (size_t)(s0 + r) * rowstride + c;
            pack_store8_hi(Khi, r * KS + (tid & 3) * 8,
                           *(const float4*)kr, *(const float4*)(kr + 4));
            pack_store8_hi(Khi, r * KS + (tid & 3) * 8 + 4,
                           *(const float4*)(kr + 8), *(const float4*)(kr + 12));
        }
        // ---- V tile: [32 swords][64 d] hi only (word packs s-pair) ----
        {
            const int s2 = tid >> 3;
            const int db = (tid & 7) * 8;
            const float* v0 = Vg + base + (size_t)(s0 + 2 * s2) * rowstride + db;
            const float* v1 = v0 + rowstride;
            float4 a0 = *(const float4*)v0, a1 = *(const float4*)(v0 + 4);
            float4 b0 = *(const float4*)v1, b1 = *(const float4*)(v1 + 4);
            *(uint4*)&Vhi[s2 * VS + db] = make_uint4(
                pack2h(a0.x, b0.x), pack2h(a0.y, b0.y),
                pack2h(a0.z, b0.z), pack2h(a0.w, b0.w));
            *(uint4*)&Vhi[s2 * VS + db + 4] = make_uint4(
                pack2h(a1.x, b1.x), pack2h(a1.y, b1.y),
                pack2h(a1.z, b1.z), pack2h(a1.w, b1.w));
        }
        __syncthreads();

        // ---- S = Q @ K^T  (4 k16 chunks over d=64) ----
        float S[8][4];
#pragma unroll
        for (int nt = 0; nt < 8; nt++)
#pragma unroll
            for (int c = 0; c < 4; c++) S[nt][c] = 0.f;

#pragma unroll
        for (int ks = 0; ks < 4; ks++) {
            const int kwb = ks * 8;
            uint32_t ah[4], al[4], bfr[8][2];
            ah[0] = Qh[(rq + g) * QS + kwb + t];
            ah[1] = Qh[(rq + g + 8) * QS + kwb + t];
            ah[2] = Qh[(rq + g) * QS + kwb + t + 4];
            ah[3] = Qh[(rq + g + 8) * QS + kwb + t + 4];
            al[0] = Ql[(rq + g) * QS + kwb + t];
            al[1] = Ql[(rq + g + 8) * QS + kwb + t];
            al[2] = Ql[(rq + g) * QS + kwb + t + 4];
            al[3] = Ql[(rq + g + 8) * QS + kwb + t + 4];
#pragma unroll
            for (int nt = 0; nt < 8; nt++) {
                bfr[nt][0] = Khi[(nt * 8 + g) * KS + kwb + t];
                bfr[nt][1] = Khi[(nt * 8 + g) * KS + kwb + t + 4];
                mma16h(S[nt], ah, bfr[nt]);
            }
#pragma unroll
            for (int nt = 0; nt < 8; nt++)
                mma16h(S[nt], al, bfr[nt]);
        }

        // ---- scale + diagonal mask ----
#pragma unroll
        for (int nt = 0; nt < 8; nt++) {
#pragma unroll
            for (int c = 0; c < 4; c++) {
                const int col = s0 + nt * 8 + 2 * t + (c & 1);
                const int row = q0 + rq + g + ((c >= 2) ? 8 : 0);
                float s = S[nt][c] * scale;
                if (col == row) s = -1e30f;
                S[nt][c] = s;
            }
        }

        // ---- online softmax ----
        float mx0 = -1e30f, mx1 = -1e30f;
#pragma unroll
        for (int nt = 0; nt < 8; nt++) {
            mx0 = fmaxf(mx0, fmaxf(S[nt][0], S[nt][1]));
            mx1 = fmaxf(mx1, fmaxf(S[nt][2], S[nt][3]));
        }
        mx0 = fmaxf(mx0, __shfl_xor_sync(0xffffffffu, mx0, 1));
        mx0 = fmaxf(mx0, __shfl_xor_sync(0xffffffffu, mx0, 2));
        mx1 = fmaxf(mx1, __shfl_xor_sync(0xffffffffu, mx1, 1));
        mx1 = fmaxf(mx1, __shfl_xor_sync(0xffffffffu, mx1, 2));

        const float mn0 = fmaxf(mrow[0], mx0);
        const float mn1 = fmaxf(mrow[1], mx1);
        const float corr0 = __expf(mrow[0] - mn0);
        const float corr1 = __expf(mrow[1] - mn1);
        mrow[0] = mn0; mrow[1] = mn1;

        float rs0 = 0.f, rs1 = 0.f;
#pragma unroll
        for (int nt = 0; nt < 8; nt++) {
            float p0 = __expf(S[nt][0] - mn0);
            float p1 = __expf(S[nt][1] - mn0);
            float p2 = __expf(S[nt][2] - mn1);
            float p3 = __expf(S[nt][3] - mn1);
            S[nt][0] = p0; S[nt][1] = p1; S[nt][2] = p2; S[nt][3] = p3;
            rs0 += p0 + p1;
            rs1 += p2 + p3;
        }
        rs0 += __shfl_xor_sync(0xffffffffu, rs0, 1);
        rs0 += __shfl_xor_sync(0xffffffffu, rs0, 2);
        rs1 += __shfl_xor_sync(0xffffffffu, rs1, 1);
        rs1 += __shfl_xor_sync(0xffffffffu, rs1, 2);

        lrow[0] = lrow[0] * corr0 + rs0;
        lrow[1] = lrow[1] * corr1 + rs1;
#pragma unroll
        for (int nt = 0; nt < 8; nt++) {
            O[nt][0] *= corr0; O[nt][1] *= corr0;
            O[nt][2] *= corr1; O[nt][3] *= corr1;
        }

        // ---- O += P @ V : C-frag of QK IS the A-frag of PV; P split in regs ----
#pragma unroll
        for (int ks = 0; ks < 4; ks++) {
            uint32_t ph[4], pl[4], vfr[8][2];
            splitpackh(S[2 * ks][0],     S[2 * ks][1],     ph[0], pl[0]);
            splitpackh(S[2 * ks][2],     S[2 * ks][3],     ph[1], pl[1]);
            splitpackh(S[2 * ks + 1][0], S[2 * ks + 1][1], ph[2], pl[2]);
            splitpackh(S[2 * ks + 1][2], S[2 * ks + 1][3], ph[3], pl[3]);
            const int swb = ks * 8;
#pragma unroll
            for (int nt = 0; nt < 8; nt++) {
                vfr[nt][0] = Vhi[(swb + t) * VS + nt * 8 + g];
                vfr[nt][1] = Vhi[(swb + t + 4) * VS + nt * 8 + g];
                mma16h(O[nt], ph, vfr[nt]);
            }
#pragma unroll
            for (int nt = 0; nt < 8; nt++)
                mma16h(O[nt], pl, vfr[nt]);
        }
        __syncthreads();   // before next tile overwrites K/V
    }

    // ---- finalize ----
    const float inv0 = 1.f / lrow[0];
    const float inv1 = 1.f / lrow[1];
#pragma unroll
    for (int nt = 0; nt < 8; nt++) {
        const int row = q0 + rq + g;
        const int col = nt * 8 + 2 * t;
        *(float2*)(Og + base + (size_t)row * rowstride + col) =
            make_float2(O[nt][0] * inv0, O[nt][1] * inv0);
        *(float2*)(Og + base + (size_t)(row + 8) * rowstride + col) =
            make_float2(O[nt][2] * inv1, O[nt][3] * inv1);
    }
}

// ---------------- launch ------------------------------------------------------
extern "C" void kernel_launch(void* const* d_in, const int* in_sizes, int n_in,
                              void* d_out, int out_size)
{
    (void)in_sizes; (void)n_in; (void)out_size;
    const float* x  = (const float*)d_in[0];
    const float* wq = (const float*)d_in[1];
    const float* wk = (const float*)d_in[2];
    const float* wv = (const float*)d_in[3];
    const float* wo = (const float*)d_in[4];
    float* out = (float*)d_out;

    float *qp, *kp, *vp, *ap;
    cudaGetSymbolAddress((void**)&qp, g_q);
    cudaGetSymbolAddress((void**)&kp, g_k);
    cudaGetSymbolAddress((void**)&vp, g_v);
    cudaGetSymbolAddress((void**)&ap, g_a);
    uint32_t *xh, *ah;
    uint32_t *wqh, *wql, *wkh, *wkl, *wvh, *wvl, *woh, *wol;
    cudaGetSymbolAddress((void**)&xh, g_xh);
    cudaGetSymbolAddress((void**)&ah, g_ah);
    cudaGetSymbolAddress((void**)&wqh, g_wqh); cudaGetSymbolAddress((void**)&wql, g_wql);
    cudaGetSymbolAddress((void**)&wkh, g_wkh); cudaGetSymbolAddress((void**)&wkl, g_wkl);
    cudaGetSymbolAddress((void**)&wvh, g_wvh); cudaGetSymbolAddress((void**)&wvl, g_wvl);
    cudaGetSymbolAddress((void**)&woh, g_woh); cudaGetSymbolAddress((void**)&wol, g_wol);

    cudaFuncSetAttribute(gemm_h, cudaFuncAttributeMaxDynamicSharedMemorySize, GEMM_SMEM_BYTES);
    cudaFuncSetAttribute(attn_kernel, cudaFuncAttributeMaxDynamicSharedMemorySize, ATTN_SMEM_BYTES);

    // 0) prepack x (hi) + weights (hi/lo)
    prepack_hi<<<1024, 256>>>(x, xh, MTOT * KW);
    prepack_hilo<<<256, 256>>>(wq, wqh, wql, DIM * KW);
    prepack_hilo<<<256, 256>>>(wk, wkh, wkl, DIM * KW);
    prepack_hilo<<<256, 256>>>(wv, wvh, wvl, DIM * KW);
    prepack_hilo<<<256, 256>>>(wo, woh, wol, DIM * KW);

    // 1) QKV projections (fused via grid.z)
    {
        dim3 grid(DIM / 128, MTOT / 128, 3);
        gemm_h<<<grid, 256, GEMM_SMEM_BYTES>>>(xh,
                                               wqh, wql, wkh, wkl, wvh, wvl,
                                               qp, kp, vp);
    }
    // 2) attention
    {
        dim3 grid(SEQLEN / BQ, BATCH * NHEADS);
        attn_kernel<<<grid, 256, ATTN_SMEM_BYTES>>>(qp, kp, vp, ap);
    }
    // 3) output projection
    prepack_hi<<<1024, 256>>>(ap, ah, MTOT * KW);
    {
        dim3 grid(DIM / 128, MTOT / 128, 1);
        gemm_h<<<grid, 256, GEMM_SMEM_BYTES>>>(ah,
                                               woh, wol, woh, wol, woh, wol,
                                               out, out, out);
    }
}

// round 10
// speedup vs baseline: 4.2923x; 1.1492x over previous
#include <cuda_runtime.h>
#include <cuda_fp16.h>
#include <math.h>
#include <stdint.h>

#define BATCH   4
#define SEQLEN  2048
#define NHEADS  16
#define HDIM    64
#define DIM     1024
#define MTOT    (BATCH * SEQLEN)   // 8192
#define KW      (DIM / 2)          // 512 packed words per token row

// ---------------- scratch (static __device__, no allocs allowed) -------------
// packed fp16 words (word = 2 elements, element 2w in low 16 bits)
__device__ uint32_t g_xh[MTOT * KW];                 // x (A-side, hi only)
__device__ uint32_t g_qh[MTOT * KW], g_ql[MTOT * KW];// Q split hi/lo
__device__ uint32_t g_kh[MTOT * KW];                 // K hi only
__device__ uint32_t g_vh[MTOT * KW];                 // V hi only
__device__ uint32_t g_ah[MTOT * KW];                 // attn out (A-side, hi only)
__device__ uint32_t g_wqh[DIM * KW], g_wql[DIM * KW];
__device__ uint32_t g_wkh[DIM * KW], g_wkl[DIM * KW];
__device__ uint32_t g_wvh[DIM * KW], g_wvl[DIM * KW];
__device__ uint32_t g_woh[DIM * KW], g_wol[DIM * KW];

// ---------------- fp16x2 helpers ---------------------------------------------
__device__ __forceinline__ uint32_t pack2h(float lo, float hi) {
    uint32_t r;
    asm("cvt.rn.f16x2.f32 %0, %1, %2;" : "=r"(r) : "f"(hi), "f"(lo));
    return r;
}
__device__ __forceinline__ void unpack2h(uint32_t w, float& lo, float& hi) {
    asm("{.reg .f16 l, h; mov.b32 {l, h}, %2; cvt.f32.f16 %0, l; cvt.f32.f16 %1, h;}"
        : "=f"(lo), "=f"(hi) : "r"(w));
}
__device__ __forceinline__ void splitpackh(float x0, float x1, uint32_t& h, uint32_t& l) {
    h = pack2h(x0, x1);
    float h0, h1;
    unpack2h(h, h0, h1);
    l = pack2h(x0 - h0, x1 - h1);
}
__device__ __forceinline__ uint32_t prmtw(uint32_t a, uint32_t b, uint32_t sel) {
    uint32_t d;
    asm("prmt.b32 %0, %1, %2, %3;" : "=r"(d) : "r"(a), "r"(b), "r"(sel));
    return d;
}
__device__ __forceinline__ void mma16h(float* d, const uint32_t* a, const uint32_t* b) {
    asm volatile(
        "mma.sync.aligned.m16n8k16.row.col.f32.f16.f16.f32 "
        "{%0,%1,%2,%3}, {%4,%5,%6,%7}, {%8,%9}, {%0,%1,%2,%3};"
        : "+f"(d[0]), "+f"(d[1]), "+f"(d[2]), "+f"(d[3])
        : "r"(a[0]), "r"(a[1]), "r"(a[2]), "r"(a[3]), "r"(b[0]), "r"(b[1]));
}
__device__ __forceinline__ uint32_t smem_u32(const void* p) {
    uint32_t a;
    asm("{ .reg .u64 t; cvta.to.shared.u64 t, %1; cvt.u32.u64 %0, t; }" : "=r"(a) : "l"(p));
    return a;
}
#define CP16(saddr, gptr) \
    asm volatile("cp.async.cg.shared.global [%0], [%1], 16;" :: "r"(saddr), "l"(gptr))
#define CP_COMMIT() asm volatile("cp.async.commit_group;" ::: "memory")
#define CP_WAIT0()  asm volatile("cp.async.wait_group 0;" ::: "memory")

// ---------------- prepack kernels --------------------------------------------
__global__ void prepack_hi(const float* __restrict__ src, uint32_t* __restrict__ hi, int nwords)
{
    int i = blockIdx.x * blockDim.x + threadIdx.x;
    int stride = gridDim.x * blockDim.x;
    for (; i < nwords; i += stride) {
        float2 v = ((const float2*)src)[i];
        hi[i] = pack2h(v.x, v.y);
    }
}
__global__ void prepack_hilo(const float* __restrict__ src, uint32_t* __restrict__ hi,
                             uint32_t* __restrict__ lo, int nwords)
{
    int i = blockIdx.x * blockDim.x + threadIdx.x;
    int stride = gridDim.x * blockDim.x;
    for (; i < nwords; i += stride) {
        float2 v = ((const float2*)src)[i];
        uint32_t h, l;
        splitpackh(v.x, v.y, h, l);
        hi[i] = h;
        lo[i] = l;
    }
}

// ---------------- GEMM: C[m][n] = sum_k A[m][k]*B[n][k]  (NT) ----------------
// CTA 128x128x32, 4 warps of 64x64. fp16 2-pass (A unsplit, B split hi/lo).
// cp.async double-buffered SMEM; epilogue writes fp32 OR packed fp16 words.
#define RSTR 20                          // words/row: 16 kwords + 4 pad
#define GARR (128 * RSTR)                // 2560 words per array
#define GSS  (3 * GARR)                  // Ah, Bh, Bl per stage
#define GEMM_SMEM_BYTES (2 * GSS * 4)    // 61440

__global__ void __launch_bounds__(128, 3)
gemm_h(const uint32_t* __restrict__ Ahg,
       const uint32_t* __restrict__ Bh0, const uint32_t* __restrict__ Bl0,
       const uint32_t* __restrict__ Bh1, const uint32_t* __restrict__ Bl1,
       const uint32_t* __restrict__ Bh2, const uint32_t* __restrict__ Bl2,
       uint32_t* __restrict__ Qh, uint32_t* __restrict__ Ql,
       uint32_t* __restrict__ Kh, uint32_t* __restrict__ Vh,
       float* __restrict__ Cf)
{
    const uint32_t* Bhg = (blockIdx.z == 0) ? Bh0 : (blockIdx.z == 1 ? Bh1 : Bh2);
    const uint32_t* Blg = (blockIdx.z == 0) ? Bl0 : (blockIdx.z == 1 ? Bl1 : Bl2);

    extern __shared__ uint32_t gsm[];
    const uint32_t sbase = smem_u32(gsm);
    const int tid  = threadIdx.x;
    const int lane = tid & 31;
    const int wid  = tid >> 5;
    const int g    = lane >> 2;
    const int t    = lane & 3;
    const int wm   = wid >> 1;           // 0..1 -> 64-row slab
    const int wn   = wid & 1;            // 0..1 -> 64-col slab
    const size_t m0 = blockIdx.y * 128;
    const size_t n0 = blockIdx.x * 128;

    const int lr  = tid >> 2;            // 0..31
    const int cw4 = (tid & 3) * 4;       // kword offset 0,4,8,12

    float acc[4][8][4];
#pragma unroll
    for (int i = 0; i < 4; i++)
#pragma unroll
        for (int j = 0; j < 8; j++)
#pragma unroll
            for (int c = 0; c < 4; c++) acc[i][j][c] = 0.f;

    const int NT = DIM / 32;             // 32 k (16 kwords) per stage

    // stage loader: 12 cp.async(16B) per thread
    auto load_stage = [&](int buf, int kw0) {
        const uint32_t sb = sbase + (uint32_t)buf * GSS * 4;
#pragma unroll
        for (int p = 0; p < 4; p++) {
            const int r = lr + p * 32;
            const int widx = r * RSTR + cw4;
            CP16(sb + widx * 4,                Ahg + (m0 + r) * KW + kw0 + cw4);
            CP16(sb + (GARR + widx) * 4,       Bhg + (n0 + r) * KW + kw0 + cw4);
            CP16(sb + (2 * GARR + widx) * 4,   Blg + (n0 + r) * KW + kw0 + cw4);
        }
    };

    load_stage(0, 0);
    CP_COMMIT();

    for (int kt = 0; kt < NT; kt++) {
        CP_WAIT0();
        __syncthreads();
        if (kt + 1 < NT) {
            load_stage((kt + 1) & 1, (kt + 1) * 16);
            CP_COMMIT();
        }

        const uint32_t* Ah = gsm + (kt & 1) * GSS;
        const uint32_t* Bh = Ah + GARR;
        const uint32_t* Bl = Ah + 2 * GARR;

#pragma unroll
        for (int ck = 0; ck < 2; ck++) {
            const int kwb = ck * 8;
            uint32_t a[4][4];
#pragma unroll
            for (int mi = 0; mi < 4; mi++) {
                const int rb = wm * 64 + mi * 16 + g;
                a[mi][0] = Ah[rb * RSTR + kwb + t];
                a[mi][1] = Ah[(rb + 8) * RSTR + kwb + t];
                a[mi][2] = Ah[rb * RSTR + kwb + t + 4];
                a[mi][3] = Ah[(rb + 8) * RSTR + kwb + t + 4];
            }
#pragma unroll
            for (int nj = 0; nj < 8; nj++) {
                const int cb = wn * 64 + nj * 8 + g;
                uint32_t bh[2], bl[2];
                bh[0] = Bh[cb * RSTR + kwb + t];
                bh[1] = Bh[cb * RSTR + kwb + t + 4];
                bl[0] = Bl[cb * RSTR + kwb + t];
                bl[1] = Bl[cb * RSTR + kwb + t + 4];
#pragma unroll
                for (int mi = 0; mi < 4; mi++) mma16h(acc[mi][nj], a[mi], bh);
#pragma unroll
                for (int mi = 0; mi < 4; mi++) mma16h(acc[mi][nj], a[mi], bl);
            }
        }
    }

    // ---- epilogue ----
    if (Cf) {
#pragma unroll
        for (int mi = 0; mi < 4; mi++) {
#pragma unroll
            for (int nj = 0; nj < 8; nj++) {
                const int row = (int)m0 + wm * 64 + mi * 16 + g;
                const int col = (int)n0 + wn * 64 + nj * 8 + 2 * t;
                *(float2*)(Cf + (size_t)row * DIM + col)       = make_float2(acc[mi][nj][0], acc[mi][nj][1]);
                *(float2*)(Cf + (size_t)(row + 8) * DIM + col) = make_float2(acc[mi][nj][2], acc[mi][nj][3]);
            }
        }
    } else {
        uint32_t* Oh = (blockIdx.z == 0) ? Qh : (blockIdx.z == 1 ? Kh : Vh);
        uint32_t* Ol = (blockIdx.z == 0) ? Ql : nullptr;
#pragma unroll
        for (int mi = 0; mi < 4; mi++) {
#pragma unroll
            for (int nj = 0; nj < 8; nj++) {
                const int row = (int)m0 + wm * 64 + mi * 16 + g;
                const int wc  = (int)(n0 >> 1) + wn * 32 + nj * 4 + t;
                if (Ol) {
                    uint32_t h0, l0, h1, l1;
                    splitpackh(acc[mi][nj][0], acc[mi][nj][1], h0, l0);
                    splitpackh(acc[mi][nj][2], acc[mi][nj][3], h1, l1);
                    Oh[(size_t)row * KW + wc]       = h0;
                    Ol[(size_t)row * KW + wc]       = l0;
                    Oh[(size_t)(row + 8) * KW + wc] = h1;
                    Ol[(size_t)(row + 8) * KW + wc] = l1;
                } else {
                    Oh[(size_t)row * KW + wc]       = pack2h(acc[mi][nj][0], acc[mi][nj][1]);
                    Oh[(size_t)(row + 8) * KW + wc] = pack2h(acc[mi][nj][2], acc[mi][nj][3]);
                }
            }
        }
    }
}

// ---------------- Flash attention (fp16 2-pass mma) with diagonal mask -------
// Inputs pre-packed fp16: Qh/Ql split, Kh/Vh hi-only. Output packed hi words.
#define BQ 128
#define BS 64
#define QS 36
#define KS 36
#define VS 72
#define ATTN_SMEM_WORDS (2 * BQ * QS + BS * KS + 32 * VS)
#define ATTN_SMEM_BYTES (ATTN_SMEM_WORDS * 4)   // 55296

__global__ void __launch_bounds__(256, 2)
attn_kernel(const uint32_t* __restrict__ Qhg, const uint32_t* __restrict__ Qlg,
            const uint32_t* __restrict__ Khg, const uint32_t* __restrict__ Vhg,
            uint32_t* __restrict__ Ohg)
{
    extern __shared__ uint32_t smw[];
    uint32_t* Qh  = smw;                    // [128][QS]
    uint32_t* Ql  = Qh + BQ * QS;
    uint32_t* Khi = Ql + BQ * QS;           // [64][KS]
    uint32_t* Vhi = Khi + BS * KS;          // [32 swords][VS]

    const int tid  = threadIdx.x;
    const int lane = tid & 31;
    const int wid  = tid >> 5;
    const int g    = lane >> 2;
    const int t    = lane & 3;
    const int tx   = tid & 15;
    const int ty   = tid >> 4;
    const int q0   = blockIdx.x * BQ;
    const int bh_i = blockIdx.y;
    const int b    = bh_i >> 4;
    const int h    = bh_i & 15;
    const float scale = 0.125f;

    const size_t rowbase = (size_t)b * SEQLEN;  // token row offset
    const int hw = h * 32;                      // head word offset in KW

    // ---- load packed Q tile [BQ][32 words] hi+lo ----
#pragma unroll
    for (int rr = 0; rr < 8; rr++) {
        const int r = ty + rr * 16;
        const size_t gidx = (rowbase + q0 + r) * KW + hw + tx * 2;
        *(uint2*)&Qh[r * QS + tx * 2] = *(const uint2*)(Qhg + gidx);
        *(uint2*)&Ql[r * QS + tx * 2] = *(const uint2*)(Qlg + gidx);
    }

    float mrow[2], lrow[2], O[8][4];
    mrow[0] = mrow[1] = -1e30f;
    lrow[0] = lrow[1] = 0.f;
#pragma unroll
    for (int nt = 0; nt < 8; nt++)
#pragma unroll
        for (int c = 0; c < 4; c++) O[nt][c] = 0.f;

    const int rq = wid * 16;
    __syncthreads();

    for (int s0 = 0; s0 < SEQLEN; s0 += BS) {
        // ---- K tile: straight packed copy [64][32 words] ----
        {
            const int r  = tid >> 2;
            const int cw = (tid & 3) * 8;
            const uint32_t* kr = Khg + (rowbase + s0 + r) * KW + hw + cw;
            *(uint4*)&Khi[r * KS + cw]     = *(const uint4*)kr;
            *(uint4*)&Khi[r * KS + cw + 4] = *(const uint4*)(kr + 4);
        }
        // ---- V tile: s-pair transpose via prmt [32 swords][64 d] ----
        {
            const int s2 = tid >> 3;
            const int db = (tid & 7) * 8;        // d offset (8 d values)
            const uint32_t* v0 = Vhg + (rowbase + s0 + 2 * s2) * KW + hw + db / 2;
            const uint32_t* v1 = v0 + KW;
            uint4 w0 = *(const uint4*)v0;
            uint4 w1 = *(const uint4*)v1;
            uint4 o0, o1;
            o0.x = prmtw(w0.x, w1.x, 0x5410); o0.y = prmtw(w0.x, w1.x, 0x7632);
            o0.z = prmtw(w0.y, w1.y, 0x5410); o0.w = prmtw(w0.y, w1.y, 0x7632);
            o1.x = prmtw(w0.z, w1.z, 0x5410); o1.y = prmtw(w0.z, w1.z, 0x7632);
            o1.z = prmtw(w0.w, w1.w, 0x5410); o1.w = prmtw(w0.w, w1.w, 0x7632);
            *(uint4*)&Vhi[s2 * VS + db]     = o0;
            *(uint4*)&Vhi[s2 * VS + db + 4] = o1;
        }
        __syncthreads();

        // ---- S = Q @ K^T ----
        float S[8][4];
#pragma unroll
        for (int nt = 0; nt < 8; nt++)
#pragma unroll
            for (int c = 0; c < 4; c++) S[nt][c] = 0.f;

#pragma unroll
        for (int ks = 0; ks < 4; ks++) {
            const int kwb = ks * 8;
            uint32_t ah[4], al[4], bfr[8][2];
            ah[0] = Qh[(rq + g) * QS + kwb + t];
            ah[1] = Qh[(rq + g + 8) * QS + kwb + t];
            ah[2] = Qh[(rq + g) * QS + kwb + t + 4];
            ah[3] = Qh[(rq + g + 8) * QS + kwb + t + 4];
            al[0] = Ql[(rq + g) * QS + kwb + t];
            al[1] = Ql[(rq + g + 8) * QS + kwb + t];
            al[2] = Ql[(rq + g) * QS + kwb + t + 4];
            al[3] = Ql[(rq + g + 8) * QS + kwb + t + 4];
#pragma unroll
            for (int nt = 0; nt < 8; nt++) {
                bfr[nt][0] = Khi[(nt * 8 + g) * KS + kwb + t];
                bfr[nt][1] = Khi[(nt * 8 + g) * KS + kwb + t + 4];
                mma16h(S[nt], ah, bfr[nt]);
            }
#pragma unroll
            for (int nt = 0; nt < 8; nt++)
                mma16h(S[nt], al, bfr[nt]);
        }

        // ---- scale + diagonal mask ----
#pragma unroll
        for (int nt = 0; nt < 8; nt++) {
#pragma unroll
            for (int c = 0; c < 4; c++) {
                const int col = s0 + nt * 8 + 2 * t + (c & 1);
                const int row = q0 + rq + g + ((c >= 2) ? 8 : 0);
                float s = S[nt][c] * scale;
                if (col == row) s = -1e30f;
                S[nt][c] = s;
            }
        }

        // ---- online softmax ----
        float mx0 = -1e30f, mx1 = -1e30f;
#pragma unroll
        for (int nt = 0; nt < 8; nt++) {
            mx0 = fmaxf(mx0, fmaxf(S[nt][0], S[nt][1]));
            mx1 = fmaxf(mx1, fmaxf(S[nt][2], S[nt][3]));
        }
        mx0 = fmaxf(mx0, __shfl_xor_sync(0xffffffffu, mx0, 1));
        mx0 = fmaxf(mx0, __shfl_xor_sync(0xffffffffu, mx0, 2));
        mx1 = fmaxf(mx1, __shfl_xor_sync(0xffffffffu, mx1, 1));
        mx1 = fmaxf(mx1, __shfl_xor_sync(0xffffffffu, mx1, 2));

        const float mn0 = fmaxf(mrow[0], mx0);
        const float mn1 = fmaxf(mrow[1], mx1);
        const float corr0 = __expf(mrow[0] - mn0);
        const float corr1 = __expf(mrow[1] - mn1);
        mrow[0] = mn0; mrow[1] = mn1;

        float rs0 = 0.f, rs1 = 0.f;
#pragma unroll
        for (int nt = 0; nt < 8; nt++) {
            float p0 = __expf(S[nt][0] - mn0);
            float p1 = __expf(S[nt][1] - mn0);
            float p2 = __expf(S[nt][2] - mn1);
            float p3 = __expf(S[nt][3] - mn1);
            S[nt][0] = p0; S[nt][1] = p1; S[nt][2] = p2; S[nt][3] = p3;
            rs0 += p0 + p1;
            rs1 += p2 + p3;
        }
        rs0 += __shfl_xor_sync(0xffffffffu, rs0, 1);
        rs0 += __shfl_xor_sync(0xffffffffu, rs0, 2);
        rs1 += __shfl_xor_sync(0xffffffffu, rs1, 1);
        rs1 += __shfl_xor_sync(0xffffffffu, rs1, 2);

        lrow[0] = lrow[0] * corr0 + rs0;
        lrow[1] = lrow[1] * corr1 + rs1;
#pragma unroll
        for (int nt = 0; nt < 8; nt++) {
            O[nt][0] *= corr0; O[nt][1] *= corr0;
            O[nt][2] *= corr1; O[nt][3] *= corr1;
        }

        // ---- O += P @ V : P split in registers; V frags cached across passes ----
#pragma unroll
        for (int ks = 0; ks < 4; ks++) {
            uint32_t ph[4], pl[4], vfr[8][2];
            splitpackh(S[2 * ks][0],     S[2 * ks][1],     ph[0], pl[0]);
            splitpackh(S[2 * ks][2],     S[2 * ks][3],     ph[1], pl[1]);
            splitpackh(S[2 * ks + 1][0], S[2 * ks + 1][1], ph[2], pl[2]);
            splitpackh(S[2 * ks + 1][2], S[2 * ks + 1][3], ph[3], pl[3]);
            const int swb = ks * 8;
#pragma unroll
            for (int nt = 0; nt < 8; nt++) {
                vfr[nt][0] = Vhi[(swb + t) * VS + nt * 8 + g];
                vfr[nt][1] = Vhi[(swb + t + 4) * VS + nt * 8 + g];
                mma16h(O[nt], ph, vfr[nt]);
            }
#pragma unroll
            for (int nt = 0; nt < 8; nt++)
                mma16h(O[nt], pl, vfr[nt]);
        }
        __syncthreads();   // before next tile overwrites K/V
    }

    // ---- finalize: write packed fp16 hi words for wo GEMM ----
    const float inv0 = 1.f / lrow[0];
    const float inv1 = 1.f / lrow[1];
#pragma unroll
    for (int nt = 0; nt < 8; nt++) {
        const int row = q0 + rq + g;
        const int wc  = hw + nt * 4 + t;
        Ohg[(rowbase + row) * KW + wc]     = pack2h(O[nt][0] * inv0, O[nt][1] * inv0);
        Ohg[(rowbase + row + 8) * KW + wc] = pack2h(O[nt][2] * inv1, O[nt][3] * inv1);
    }
}

// ---------------- launch ------------------------------------------------------
extern "C" void kernel_launch(void* const* d_in, const int* in_sizes, int n_in,
                              void* d_out, int out_size)
{
    (void)in_sizes; (void)n_in; (void)out_size;
    const float* x  = (const float*)d_in[0];
    const float* wq = (const float*)d_in[1];
    const float* wk = (const float*)d_in[2];
    const float* wv = (const float*)d_in[3];
    const float* wo = (const float*)d_in[4];
    float* out = (float*)d_out;

    uint32_t *xh, *qh, *ql, *kh, *vh, *ah;
    uint32_t *wqh, *wql, *wkh, *wkl, *wvh, *wvl, *woh, *wol;
    cudaGetSymbolAddress((void**)&xh, g_xh);
    cudaGetSymbolAddress((void**)&qh, g_qh);  cudaGetSymbolAddress((void**)&ql, g_ql);
    cudaGetSymbolAddress((void**)&kh, g_kh);  cudaGetSymbolAddress((void**)&vh, g_vh);
    cudaGetSymbolAddress((void**)&ah, g_ah);
    cudaGetSymbolAddress((void**)&wqh, g_wqh); cudaGetSymbolAddress((void**)&wql, g_wql);
    cudaGetSymbolAddress((void**)&wkh, g_wkh); cudaGetSymbolAddress((void**)&wkl, g_wkl);
    cudaGetSymbolAddress((void**)&wvh, g_wvh); cudaGetSymbolAddress((void**)&wvl, g_wvl);
    cudaGetSymbolAddress((void**)&woh, g_woh); cudaGetSymbolAddress((void**)&wol, g_wol);

    cudaFuncSetAttribute(gemm_h, cudaFuncAttributeMaxDynamicSharedMemorySize, GEMM_SMEM_BYTES);
    cudaFuncSetAttribute(attn_kernel, cudaFuncAttributeMaxDynamicSharedMemorySize, ATTN_SMEM_BYTES);

    // 0) prepack x (hi) + weights (hi/lo)
    prepack_hi<<<1024, 256>>>(x, xh, MTOT * KW);
    prepack_hilo<<<256, 256>>>(wq, wqh, wql, DIM * KW);
    prepack_hilo<<<256, 256>>>(wk, wkh, wkl, DIM * KW);
    prepack_hilo<<<256, 256>>>(wv, wvh, wvl, DIM * KW);
    prepack_hilo<<<256, 256>>>(wo, woh, wol, DIM * KW);

    // 1) QKV projections -> packed fp16 intermediates (fused via grid.z)
    {
        dim3 grid(DIM / 128, MTOT / 128, 3);
        gemm_h<<<grid, 128, GEMM_SMEM_BYTES>>>(xh,
                                               wqh, wql, wkh, wkl, wvh, wvl,
                                               qh, ql, kh, vh, nullptr);
    }
    // 2) attention (packed in, packed out)
    {
        dim3 grid(SEQLEN / BQ, BATCH * NHEADS);
        attn_kernel<<<grid, 256, ATTN_SMEM_BYTES>>>(qh, ql, kh, vh, ah);
    }
    // 3) output projection -> fp32 out
    {
        dim3 grid(DIM / 128, MTOT / 128, 1);
        gemm_h<<<grid, 128, GEMM_SMEM_BYTES>>>(ah,
                                               woh, wol, woh, wol, woh, wol,
                                               nullptr, nullptr, nullptr, nullptr,
                                               out);
    }
}

// round 12
// speedup vs baseline: 5.5504x; 1.2931x over previous
#include <cuda_runtime.h>
#include <cuda_fp16.h>
#include <math.h>
#include <stdint.h>

#define BATCH   4
#define SEQLEN  2048
#define NHEADS  16
#define HDIM    64
#define DIM     1024
#define MTOT    (BATCH * SEQLEN)   // 8192
#define KW      (DIM / 2)          // 512 packed words per token row

// ---------------- scratch (static __device__, no allocs allowed) -------------
__device__ uint32_t g_xh[MTOT * KW];                 // x (A-side, hi only)
__device__ uint32_t g_qh[MTOT * KW], g_ql[MTOT * KW];// Q split hi/lo
__device__ uint32_t g_kh[MTOT * KW];                 // K hi only
__device__ uint32_t g_vh[MTOT * KW];                 // V hi only
__device__ uint32_t g_ah[MTOT * KW];                 // attn out (A-side, hi only)
__device__ uint32_t g_wqh[DIM * KW];                 // QKV weights: hi only
__device__ uint32_t g_wkh[DIM * KW];
__device__ uint32_t g_wvh[DIM * KW];
__device__ uint32_t g_woh[DIM * KW], g_wol[DIM * KW];// wo split hi/lo

// ---------------- fp16x2 helpers ---------------------------------------------
__device__ __forceinline__ uint32_t pack2h(float lo, float hi) {
    uint32_t r;
    asm("cvt.rn.f16x2.f32 %0, %1, %2;" : "=r"(r) : "f"(hi), "f"(lo));
    return r;
}
__device__ __forceinline__ void unpack2h(uint32_t w, float& lo, float& hi) {
    asm("{.reg .f16 l, h; mov.b32 {l, h}, %2; cvt.f32.f16 %0, l; cvt.f32.f16 %1, h;}"
        : "=f"(lo), "=f"(hi) : "r"(w));
}
__device__ __forceinline__ void splitpackh(float x0, float x1, uint32_t& h, uint32_t& l) {
    h = pack2h(x0, x1);
    float h0, h1;
    unpack2h(h, h0, h1);
    l = pack2h(x0 - h0, x1 - h1);
}
__device__ __forceinline__ uint32_t prmtw(uint32_t a, uint32_t b, uint32_t sel) {
    uint32_t d;
    asm("prmt.b32 %0, %1, %2, %3;" : "=r"(d) : "r"(a), "r"(b), "r"(sel));
    return d;
}
__device__ __forceinline__ void mma16h(float* d, const uint32_t* a, const uint32_t* b) {
    asm volatile(
        "mma.sync.aligned.m16n8k16.row.col.f32.f16.f16.f32 "
        "{%0,%1,%2,%3}, {%4,%5,%6,%7}, {%8,%9}, {%0,%1,%2,%3};"
        : "+f"(d[0]), "+f"(d[1]), "+f"(d[2]), "+f"(d[3])
        : "r"(a[0]), "r"(a[1]), "r"(a[2]), "r"(a[3]), "r"(b[0]), "r"(b[1]));
}
__device__ __forceinline__ uint32_t smem_u32(const void* p) {
    uint32_t a;
    asm("{ .reg .u64 t; cvta.to.shared.u64 t, %1; cvt.u32.u64 %0, t; }" : "=r"(a) : "l"(p));
    return a;
}
#define CP16(saddr, gptr) \
    asm volatile("cp.async.cg.shared.global [%0], [%1], 16;" :: "r"(saddr), "l"(gptr))
#define CP_COMMIT() asm volatile("cp.async.commit_group;" ::: "memory")
#define CP_WAIT0()  asm volatile("cp.async.wait_group 0;" ::: "memory")

// ---------------- prepack kernels --------------------------------------------
__global__ void prepack_hi(const float* __restrict__ src, uint32_t* __restrict__ hi, int nwords)
{
    int i = blockIdx.x * blockDim.x + threadIdx.x;
    int stride = gridDim.x * blockDim.x;
    for (; i < nwords; i += stride) {
        float2 v = ((const float2*)src)[i];
        hi[i] = pack2h(v.x, v.y);
    }
}
__global__ void prepack_hilo(const float* __restrict__ src, uint32_t* __restrict__ hi,
                             uint32_t* __restrict__ lo, int nwords)
{
    int i = blockIdx.x * blockDim.x + threadIdx.x;
    int stride = gridDim.x * blockDim.x;
    for (; i < nwords; i += stride) {
        float2 v = ((const float2*)src)[i];
        uint32_t h, l;
        splitpackh(v.x, v.y, h, l);
        hi[i] = h;
        lo[i] = l;
    }
}

// ---------------- GEMM: C[m][n] = sum_k A[m][k]*B[n][k]  (NT) ----------------
// CTA 128x128x32, 4 warps of 64x64. A unsplit fp16.
// SPLITB: B 2-pass hi/lo (wo path) vs single-pass hi (QKV path).
#define RSTR 20                          // words/row: 16 kwords + 4 pad
#define GARR (128 * RSTR)                // 2560 words per array
#define GEMM_SMEM_SPLIT  (2 * 3 * GARR * 4)  // 61440
#define GEMM_SMEM_SINGLE (2 * 2 * GARR * 4)  // 40960

template <bool SPLITB>
__global__ void __launch_bounds__(128, 3)
gemm_h(const uint32_t* __restrict__ Ahg,
       const uint32_t* __restrict__ Bh0, const uint32_t* __restrict__ Bl0,
       const uint32_t* __restrict__ Bh1,
       const uint32_t* __restrict__ Bh2,
       uint32_t* __restrict__ Qh, uint32_t* __restrict__ Ql,
       uint32_t* __restrict__ Kh, uint32_t* __restrict__ Vh,
       float* __restrict__ Cf)
{
    const int NARR = SPLITB ? 3 : 2;
    const uint32_t* Bhg = (blockIdx.z == 0) ? Bh0 : (blockIdx.z == 1 ? Bh1 : Bh2);

    extern __shared__ uint32_t gsm[];
    const uint32_t sbase = smem_u32(gsm);
    const int tid  = threadIdx.x;
    const int lane = tid & 31;
    const int wid  = tid >> 5;
    const int g    = lane >> 2;
    const int t    = lane & 3;
    const int wm   = wid >> 1;
    const int wn   = wid & 1;
    const size_t m0 = blockIdx.y * 128;
    const size_t n0 = blockIdx.x * 128;

    const int lr  = tid >> 2;            // 0..31
    const int cw4 = (tid & 3) * 4;       // kword offset

    float acc[4][8][4];
#pragma unroll
    for (int i = 0; i < 4; i++)
#pragma unroll
        for (int j = 0; j < 8; j++)
#pragma unroll
            for (int c = 0; c < 4; c++) acc[i][j][c] = 0.f;

    const int NT = DIM / 32;

    auto load_stage = [&](int buf, int kw0) {
        const uint32_t sb = sbase + (uint32_t)buf * NARR * GARR * 4;
#pragma unroll
        for (int p = 0; p < 4; p++) {
            const int r = lr + p * 32;
            const int widx = r * RSTR + cw4;
            CP16(sb + widx * 4,              Ahg + (m0 + r) * KW + kw0 + cw4);
            CP16(sb + (GARR + widx) * 4,     Bhg + (n0 + r) * KW + kw0 + cw4);
            if (SPLITB)
                CP16(sb + (2 * GARR + widx) * 4, Bl0 + (n0 + r) * KW + kw0 + cw4);
        }
    };

    load_stage(0, 0);
    CP_COMMIT();

    for (int kt = 0; kt < NT; kt++) {
        CP_WAIT0();
        __syncthreads();
        if (kt + 1 < NT) {
            load_stage((kt + 1) & 1, (kt + 1) * 16);
            CP_COMMIT();
        }

        const uint32_t* Ah = gsm + (kt & 1) * NARR * GARR;
        const uint32_t* Bh = Ah + GARR;
        const uint32_t* Bl = Ah + 2 * GARR;   // valid only if SPLITB

#pragma unroll
        for (int ck = 0; ck < 2; ck++) {
            const int kwb = ck * 8;
            uint32_t a[4][4];
#pragma unroll
            for (int mi = 0; mi < 4; mi++) {
                const int rb = wm * 64 + mi * 16 + g;
                a[mi][0] = Ah[rb * RSTR + kwb + t];
                a[mi][1] = Ah[(rb + 8) * RSTR + kwb + t];
                a[mi][2] = Ah[rb * RSTR + kwb + t + 4];
                a[mi][3] = Ah[(rb + 8) * RSTR + kwb + t + 4];
            }
#pragma unroll
            for (int nj = 0; nj < 8; nj++) {
                const int cb = wn * 64 + nj * 8 + g;
                uint32_t bh[2];
                bh[0] = Bh[cb * RSTR + kwb + t];
                bh[1] = Bh[cb * RSTR + kwb + t + 4];
#pragma unroll
                for (int mi = 0; mi < 4; mi++) mma16h(acc[mi][nj], a[mi], bh);
                if (SPLITB) {
                    uint32_t bl[2];
                    bl[0] = Bl[cb * RSTR + kwb + t];
                    bl[1] = Bl[cb * RSTR + kwb + t + 4];
#pragma unroll
                    for (int mi = 0; mi < 4; mi++) mma16h(acc[mi][nj], a[mi], bl);
                }
            }
        }
    }

    // ---- epilogue ----
    if (Cf) {
#pragma unroll
        for (int mi = 0; mi < 4; mi++) {
#pragma unroll
            for (int nj = 0; nj < 8; nj++) {
                const int row = (int)m0 + wm * 64 + mi * 16 + g;
                const int col = (int)n0 + wn * 64 + nj * 8 + 2 * t;
                *(float2*)(Cf + (size_t)row * DIM + col)       = make_float2(acc[mi][nj][0], acc[mi][nj][1]);
                *(float2*)(Cf + (size_t)(row + 8) * DIM + col) = make_float2(acc[mi][nj][2], acc[mi][nj][3]);
            }
        }
    } else {
        uint32_t* Oh = (blockIdx.z == 0) ? Qh : (blockIdx.z == 1 ? Kh : Vh);
        uint32_t* Ol = (blockIdx.z == 0) ? Ql : nullptr;
#pragma unroll
        for (int mi = 0; mi < 4; mi++) {
#pragma unroll
            for (int nj = 0; nj < 8; nj++) {
                const int row = (int)m0 + wm * 64 + mi * 16 + g;
                const int wc  = (int)(n0 >> 1) + wn * 32 + nj * 4 + t;
                if (Ol) {
                    uint32_t h0, l0, h1, l1;
                    splitpackh(acc[mi][nj][0], acc[mi][nj][1], h0, l0);
                    splitpackh(acc[mi][nj][2], acc[mi][nj][3], h1, l1);
                    Oh[(size_t)row * KW + wc]       = h0;
                    Ol[(size_t)row * KW + wc]       = l0;
                    Oh[(size_t)(row + 8) * KW + wc] = h1;
                    Ol[(size_t)(row + 8) * KW + wc] = l1;
                } else {
                    Oh[(size_t)row * KW + wc]       = pack2h(acc[mi][nj][0], acc[mi][nj][1]);
                    Oh[(size_t)(row + 8) * KW + wc] = pack2h(acc[mi][nj][2], acc[mi][nj][3]);
                }
            }
        }
    }
}

// ---------------- Flash attention (fp16) with diagonal mask ------------------
// QK 2-pass (Q split hi/lo); PV single pass (P hi only).
// K/V tiles double-buffered: LDG-prefetch regs -> compute -> STS -> 1 sync.
#define BQ 128
#define BS 64
#define QS 36
#define KS 36
#define VS 72
#define KBUF (BS * KS)   // 2304 words per K buffer
#define VBUF (32 * VS)   // 2304 words per V buffer
#define ATTN_SMEM_WORDS (2 * BQ * QS + 2 * KBUF + 2 * VBUF)
#define ATTN_SMEM_BYTES (ATTN_SMEM_WORDS * 4)   // 73728

__global__ void __launch_bounds__(256, 2)
attn_kernel(const uint32_t* __restrict__ Qhg, const uint32_t* __restrict__ Qlg,
            const uint32_t* __restrict__ Khg, const uint32_t* __restrict__ Vhg,
            uint32_t* __restrict__ Ohg)
{
    extern __shared__ uint32_t smw[];
    uint32_t* Qh  = smw;                    // [128][QS]
    uint32_t* Ql  = Qh + BQ * QS;
    uint32_t* Kb  = Ql + BQ * QS;           // 2 x [64][KS]
    uint32_t* Vb  = Kb + 2 * KBUF;          // 2 x [32][VS]

    const int tid  = threadIdx.x;
    const int lane = tid & 31;
    const int wid  = tid >> 5;
    const int g    = lane >> 2;
    const int t    = lane & 3;
    const int tx   = tid & 15;
    const int ty   = tid >> 4;
    const int q0   = blockIdx.x * BQ;
    const int bh_i = blockIdx.y;
    const int b    = bh_i >> 4;
    const int h    = bh_i & 15;
    const float scale = 0.125f;

    const size_t rowbase = (size_t)b * SEQLEN;
    const int hw = h * 32;

    // loader lane mapping
    const int kr_r  = tid >> 2;          // K: row 0..63
    const int kr_cw = (tid & 3) * 8;     // K: 8 words
    const int v_s2  = tid >> 3;          // V: sword 0..31
    const int v_db  = (tid & 7) * 8;     // V: d offset

    // ---- load packed Q tile [BQ][32 words] hi+lo ----
#pragma unroll
    for (int rr = 0; rr < 8; rr++) {
        const int r = ty + rr * 16;
        const size_t gidx = (rowbase + q0 + r) * KW + hw + tx * 2;
        *(uint2*)&Qh[r * QS + tx * 2] = *(const uint2*)(Qhg + gidx);
        *(uint2*)&Ql[r * QS + tx * 2] = *(const uint2*)(Qlg + gidx);
    }

    float mrow[2], lrow[2], O[8][4];
    mrow[0] = mrow[1] = -1e30f;
    lrow[0] = lrow[1] = 0.f;
#pragma unroll
    for (int nt = 0; nt < 8; nt++)
#pragma unroll
        for (int c = 0; c < 4; c++) O[nt][c] = 0.f;

    const int rq = wid * 16;

    // ---- tile 0 load + store to buffer 0 ----
    {
        const uint32_t* kr = Khg + (rowbase + kr_r) * KW + hw + kr_cw;
        uint4 k0 = *(const uint4*)kr;
        uint4 k1 = *(const uint4*)(kr + 4);
        const uint32_t* vp = Vhg + (rowbase + 2 * v_s2) * KW + hw + v_db / 2;
        uint4 w0 = *(const uint4*)vp;
        uint4 w1 = *(const uint4*)(vp + KW);
        *(uint4*)&Kb[kr_r * KS + kr_cw]     = k0;
        *(uint4*)&Kb[kr_r * KS + kr_cw + 4] = k1;
        uint4 o0, o1;
        o0.x = prmtw(w0.x, w1.x, 0x5410); o0.y = prmtw(w0.x, w1.x, 0x7632);
        o0.z = prmtw(w0.y, w1.y, 0x5410); o0.w = prmtw(w0.y, w1.y, 0x7632);
        o1.x = prmtw(w0.z, w1.z, 0x5410); o1.y = prmtw(w0.z, w1.z, 0x7632);
        o1.z = prmtw(w0.w, w1.w, 0x5410); o1.w = prmtw(w0.w, w1.w, 0x7632);
        *(uint4*)&Vb[v_s2 * VS + v_db]     = o0;
        *(uint4*)&Vb[v_s2 * VS + v_db + 4] = o1;
    }
    __syncthreads();

    const int NTILES = SEQLEN / BS;
    for (int it = 0; it < NTILES; it++) {
        const int s0 = it * BS;
        const bool has = (it + 1 < NTILES);
        const uint32_t* Khi = Kb + (it & 1) * KBUF;
        const uint32_t* Vhi = Vb + (it & 1) * VBUF;

        // prefetch next tile into registers (overlaps with compute)
        uint4 nk0, nk1, nw0, nw1;
        if (has) {
            const uint32_t* kr = Khg + (rowbase + s0 + BS + kr_r) * KW + hw + kr_cw;
            nk0 = *(const uint4*)kr;
            nk1 = *(const uint4*)(kr + 4);
            const uint32_t* vp = Vhg + (rowbase + s0 + BS + 2 * v_s2) * KW + hw + v_db / 2;
            nw0 = *(const uint4*)vp;
            nw1 = *(const uint4*)(vp + KW);
        }

        // ---- S = Q @ K^T  (2-pass: Q hi + Q lo) ----
        float S[8][4];
#pragma unroll
        for (int nt = 0; nt < 8; nt++)
#pragma unroll
            for (int c = 0; c < 4; c++) S[nt][c] = 0.f;

#pragma unroll
        for (int ks = 0; ks < 4; ks++) {
            const int kwb = ks * 8;
            uint32_t ah[4], al[4], bfr[8][2];
            ah[0] = Qh[(rq + g) * QS + kwb + t];
            ah[1] = Qh[(rq + g + 8) * QS + kwb + t];
            ah[2] = Qh[(rq + g) * QS + kwb + t + 4];
            ah[3] = Qh[(rq + g + 8) * QS + kwb + t + 4];
            al[0] = Ql[(rq + g) * QS + kwb + t];
            al[1] = Ql[(rq + g + 8) * QS + kwb + t];
            al[2] = Ql[(rq + g) * QS + kwb + t + 4];
            al[3] = Ql[(rq + g + 8) * QS + kwb + t + 4];
#pragma unroll
            for (int nt = 0; nt < 8; nt++) {
                bfr[nt][0] = Khi[(nt * 8 + g) * KS + kwb + t];
                bfr[nt][1] = Khi[(nt * 8 + g) * KS + kwb + t + 4];
                mma16h(S[nt], ah, bfr[nt]);
            }
#pragma unroll
            for (int nt = 0; nt < 8; nt++)
                mma16h(S[nt], al, bfr[nt]);
        }

        // ---- scale + diagonal mask ----
#pragma unroll
        for (int nt = 0; nt < 8; nt++) {
#pragma unroll
            for (int c = 0; c < 4; c++) {
                const int col = s0 + nt * 8 + 2 * t + (c & 1);
                const int row = q0 + rq + g + ((c >= 2) ? 8 : 0);
                float s = S[nt][c] * scale;
                if (col == row) s = -1e30f;
                S[nt][c] = s;
            }
        }

        // ---- online softmax ----
        float mx0 = -1e30f, mx1 = -1e30f;
#pragma unroll
        for (int nt = 0; nt < 8; nt++) {
            mx0 = fmaxf(mx0, fmaxf(S[nt][0], S[nt][1]));
            mx1 = fmaxf(mx1, fmaxf(S[nt][2], S[nt][3]));
        }
        mx0 = fmaxf(mx0, __shfl_xor_sync(0xffffffffu, mx0, 1));
        mx0 = fmaxf(mx0, __shfl_xor_sync(0xffffffffu, mx0, 2));
        mx1 = fmaxf(mx1, __shfl_xor_sync(0xffffffffu, mx1, 1));
        mx1 = fmaxf(mx1, __shfl_xor_sync(0xffffffffu, mx1, 2));

        const float mn0 = fmaxf(mrow[0], mx0);
        const float mn1 = fmaxf(mrow[1], mx1);
        const float corr0 = __expf(mrow[0] - mn0);
        const float corr1 = __expf(mrow[1] - mn1);
        mrow[0] = mn0; mrow[1] = mn1;

        float rs0 = 0.f, rs1 = 0.f;
#pragma unroll
        for (int nt = 0; nt < 8; nt++) {
            float p0 = __expf(S[nt][0] - mn0);
            float p1 = __expf(S[nt][1] - mn0);
            float p2 = __expf(S[nt][2] - mn1);
            float p3 = __expf(S[nt][3] - mn1);
            S[nt][0] = p0; S[nt][1] = p1; S[nt][2] = p2; S[nt][3] = p3;
            rs0 += p0 + p1;
            rs1 += p2 + p3;
        }
        rs0 += __shfl_xor_sync(0xffffffffu, rs0, 1);
        rs0 += __shfl_xor_sync(0xffffffffu, rs0, 2);
        rs1 += __shfl_xor_sync(0xffffffffu, rs1, 1);
        rs1 += __shfl_xor_sync(0xffffffffu, rs1, 2);

        lrow[0] = lrow[0] * corr0 + rs0;
        lrow[1] = lrow[1] * corr1 + rs1;
#pragma unroll
        for (int nt = 0; nt < 8; nt++) {
            O[nt][0] *= corr0; O[nt][1] *= corr0;
            O[nt][2] *= corr1; O[nt][3] *= corr1;
        }

        // ---- O += P @ V : single pass (P hi only) ----
#pragma unroll
        for (int ks = 0; ks < 4; ks++) {
            uint32_t ph[4];
            ph[0] = pack2h(S[2 * ks][0],     S[2 * ks][1]);
            ph[1] = pack2h(S[2 * ks][2],     S[2 * ks][3]);
            ph[2] = pack2h(S[2 * ks + 1][0], S[2 * ks + 1][1]);
            ph[3] = pack2h(S[2 * ks + 1][2], S[2 * ks + 1][3]);
            const int swb = ks * 8;
#pragma unroll
            for (int nt = 0; nt < 8; nt++) {
                uint32_t vfr[2];
                vfr[0] = Vhi[(swb + t) * VS + nt * 8 + g];
                vfr[1] = Vhi[(swb + t + 4) * VS + nt * 8 + g];
                mma16h(O[nt], ph, vfr);
            }
        }

        // ---- store prefetched tile into the other buffer ----
        if (has) {
            uint32_t* Kn = Kb + ((it + 1) & 1) * KBUF;
            uint32_t* Vn = Vb + ((it + 1) & 1) * VBUF;
            *(uint4*)&Kn[kr_r * KS + kr_cw]     = nk0;
            *(uint4*)&Kn[kr_r * KS + kr_cw + 4] = nk1;
            uint4 o0, o1;
            o0.x = prmtw(nw0.x, nw1.x, 0x5410); o0.y = prmtw(nw0.x, nw1.x, 0x7632);
            o0.z = prmtw(nw0.y, nw1.y, 0x5410); o0.w = prmtw(nw0.y, nw1.y, 0x7632);
            o1.x = prmtw(nw0.z, nw1.z, 0x5410); o1.y = prmtw(nw0.z, nw1.z, 0x7632);
            o1.z = prmtw(nw0.w, nw1.w, 0x5410); o1.w = prmtw(nw0.w, nw1.w, 0x7632);
            *(uint4*)&Vn[v_s2 * VS + v_db]     = o0;
            *(uint4*)&Vn[v_s2 * VS + v_db + 4] = o1;
        }
        __syncthreads();
    }

    // ---- finalize: write packed fp16 hi words for wo GEMM ----
    const float inv0 = 1.f / lrow[0];
    const float inv1 = 1.f / lrow[1];
#pragma unroll
    for (int nt = 0; nt < 8; nt++) {
        const int row = q0 + rq + g;
        const int wc  = hw + nt * 4 + t;
        Ohg[(rowbase + row) * KW + wc]     = pack2h(O[nt][0] * inv0, O[nt][1] * inv0);
        Ohg[(rowbase + row + 8) * KW + wc] = pack2h(O[nt][2] * inv1, O[nt][3] * inv1);
    }
}

// ---------------- launch ------------------------------------------------------
extern "C" void kernel_launch(void* const* d_in, const int* in_sizes, int n_in,
                              void* d_out, int out_size)
{
    (void)in_sizes; (void)n_in; (void)out_size;
    const float* x  = (const float*)d_in[0];
    const float* wq = (const float*)d_in[1];
    const float* wk = (const float*)d_in[2];
    const float* wv = (const float*)d_in[3];
    const float* wo = (const float*)d_in[4];
    float* out = (float*)d_out;

    uint32_t *xh, *qh, *ql, *kh, *vh, *ah;
    uint32_t *wqh, *wkh, *wvh, *woh, *wol;
    cudaGetSymbolAddress((void**)&xh, g_xh);
    cudaGetSymbolAddress((void**)&qh, g_qh);  cudaGetSymbolAddress((void**)&ql, g_ql);
    cudaGetSymbolAddress((void**)&kh, g_kh);  cudaGetSymbolAddress((void**)&vh, g_vh);
    cudaGetSymbolAddress((void**)&ah, g_ah);
    cudaGetSymbolAddress((void**)&wqh, g_wqh);
    cudaGetSymbolAddress((void**)&wkh, g_wkh);
    cudaGetSymbolAddress((void**)&wvh, g_wvh);
    cudaGetSymbolAddress((void**)&woh, g_woh); cudaGetSymbolAddress((void**)&wol, g_wol);

    cudaFuncSetAttribute(gemm_h<false>, cudaFuncAttributeMaxDynamicSharedMemorySize, GEMM_SMEM_SINGLE);
    cudaFuncSetAttribute(gemm_h<true>,  cudaFuncAttributeMaxDynamicSharedMemorySize, GEMM_SMEM_SPLIT);
    cudaFuncSetAttribute(attn_kernel, cudaFuncAttributeMaxDynamicSharedMemorySize, ATTN_SMEM_BYTES);

    // 0) prepack x + weights (QKV weights hi-only; wo split)
    prepack_hi<<<1024, 256>>>(x, xh, MTOT * KW);
    prepack_hi<<<256, 256>>>(wq, wqh, DIM * KW);
    prepack_hi<<<256, 256>>>(wk, wkh, DIM * KW);
    prepack_hi<<<256, 256>>>(wv, wvh, DIM * KW);
    prepack_hilo<<<256, 256>>>(wo, woh, wol, DIM * KW);

    // 1) QKV projections, single-pass B (fused via grid.z)
    {
        dim3 grid(DIM / 128, MTOT / 128, 3);
        gemm_h<false><<<grid, 128, GEMM_SMEM_SINGLE>>>(xh,
                                                       wqh, nullptr, wkh, wvh,
                                                       qh, ql, kh, vh, nullptr);
    }
    // 2) attention (packed in, packed out)
    {
        dim3 grid(SEQLEN / BQ, BATCH * NHEADS);
        attn_kernel<<<grid, 256, ATTN_SMEM_BYTES>>>(qh, ql, kh, vh, ah);
    }
    // 3) output projection, 2-pass B -> fp32 out
    {
        dim3 grid(DIM / 128, MTOT / 128, 1);
        gemm_h<true><<<grid, 128, GEMM_SMEM_SPLIT>>>(ah,
                                                     woh, wol, woh, woh,
                                                     nullptr, nullptr, nullptr, nullptr,
                                                     out);
    }
}

// round 15
// speedup vs baseline: 5.9985x; 1.0807x over previous
#include <cuda_runtime.h>
#include <cuda_fp16.h>
#include <math.h>
#include <stdint.h>

#define BATCH   4
#define SEQLEN  2048
#define NHEADS  16
#define HDIM    64
#define DIM     1024
#define MTOT    (BATCH * SEQLEN)   // 8192
#define KW      (DIM / 2)          // 512 packed words per token row

// ---------------- scratch (static __device__, no allocs allowed) -------------
__device__ uint32_t g_xh[MTOT * KW];                 // x (A-side, hi only)
__device__ uint32_t g_qh[MTOT * KW], g_ql[MTOT * KW];// Q split hi/lo
__device__ uint32_t g_kh[MTOT * KW];                 // K hi only
__device__ uint32_t g_vh[MTOT * KW];                 // V hi only
__device__ uint32_t g_ah[MTOT * KW];                 // attn out (A-side, hi only)
__device__ uint32_t g_wqh[DIM * KW];                 // all weights: hi only
__device__ uint32_t g_wkh[DIM * KW];
__device__ uint32_t g_wvh[DIM * KW];
__device__ uint32_t g_woh[DIM * KW];

// ---------------- fp16x2 helpers ---------------------------------------------
__device__ __forceinline__ uint32_t pack2h(float lo, float hi) {
    uint32_t r;
    asm("cvt.rn.f16x2.f32 %0, %1, %2;" : "=r"(r) : "f"(hi), "f"(lo));
    return r;
}
__device__ __forceinline__ void unpack2h(uint32_t w, float& lo, float& hi) {
    asm("{.reg .f16 l, h; mov.b32 {l, h}, %2; cvt.f32.f16 %0, l; cvt.f32.f16 %1, h;}"
        : "=f"(lo), "=f"(hi) : "r"(w));
}
__device__ __forceinline__ void splitpackh(float x0, float x1, uint32_t& h, uint32_t& l) {
    h = pack2h(x0, x1);
    float h0, h1;
    unpack2h(h, h0, h1);
    l = pack2h(x0 - h0, x1 - h1);
}
__device__ __forceinline__ uint32_t prmtw(uint32_t a, uint32_t b, uint32_t sel) {
    uint32_t d;
    asm("prmt.b32 %0, %1, %2, %3;" : "=r"(d) : "r"(a), "r"(b), "r"(sel));
    return d;
}
__device__ __forceinline__ void mma16h(float* d, const uint32_t* a, const uint32_t* b) {
    asm volatile(
        "mma.sync.aligned.m16n8k16.row.col.f32.f16.f16.f32 "
        "{%0,%1,%2,%3}, {%4,%5,%6,%7}, {%8,%9}, {%0,%1,%2,%3};"
        : "+f"(d[0]), "+f"(d[1]), "+f"(d[2]), "+f"(d[3])
        : "r"(a[0]), "r"(a[1]), "r"(a[2]), "r"(a[3]), "r"(b[0]), "r"(b[1]));
}
__device__ __forceinline__ uint32_t smem_u32(const void* p) {
    uint32_t a;
    asm("{ .reg .u64 t; cvta.to.shared.u64 t, %1; cvt.u32.u64 %0, t; }" : "=r"(a) : "l"(p));
    return a;
}
#define CP16(saddr, gptr) \
    asm volatile("cp.async.cg.shared.global [%0], [%1], 16;" :: "r"(saddr), "l"(gptr))
#define CP_COMMIT() asm volatile("cp.async.commit_group;" ::: "memory")
#define CP_WAIT0()  asm volatile("cp.async.wait_group 0;" ::: "memory")

// ---------------- prepack kernel ----------------------------------------------
__global__ void prepack_hi(const float* __restrict__ src, uint32_t* __restrict__ hi, int nwords)
{
    int i = blockIdx.x * blockDim.x + threadIdx.x;
    int stride = gridDim.x * blockDim.x;
    for (; i < nwords; i += stride) {
        float2 v = ((const float2*)src)[i];
        hi[i] = pack2h(v.x, v.y);
    }
}

// ---------------- GEMM: C[m][n] = sum_k A[m][k]*B[n][k]  (NT) ----------------
// CTA 128x128x32, 4 warps of 64x64. A and B both fp16 hi-only (single pass).
#define RSTR 20                          // words/row: 16 kwords + 4 pad
#define GARR (128 * RSTR)                // 2560 words per array
#define GEMM_SMEM_BYTES (2 * 2 * GARR * 4)   // 40960

__global__ void __launch_bounds__(128, 3)
gemm_h(const uint32_t* __restrict__ Ahg,
       const uint32_t* __restrict__ Bh0, const uint32_t* __restrict__ Bh1,
       const uint32_t* __restrict__ Bh2,
       uint32_t* __restrict__ Qh, uint32_t* __restrict__ Ql,
       uint32_t* __restrict__ Kh, uint32_t* __restrict__ Vh,
       float* __restrict__ Cf)
{
    const uint32_t* Bhg = (blockIdx.z == 0) ? Bh0 : (blockIdx.z == 1 ? Bh1 : Bh2);

    extern __shared__ uint32_t gsm[];
    const uint32_t sbase = smem_u32(gsm);
    const int tid  = threadIdx.x;
    const int lane = tid & 31;
    const int wid  = tid >> 5;
    const int g    = lane >> 2;
    const int t    = lane & 3;
    const int wm   = wid >> 1;
    const int wn   = wid & 1;
    const size_t m0 = blockIdx.y * 128;
    const size_t n0 = blockIdx.x * 128;

    const int lr  = tid >> 2;            // 0..31
    const int cw4 = (tid & 3) * 4;       // kword offset

    float acc[4][8][4];
#pragma unroll
    for (int i = 0; i < 4; i++)
#pragma unroll
        for (int j = 0; j < 8; j++)
#pragma unroll
            for (int c = 0; c < 4; c++) acc[i][j][c] = 0.f;

    const int NT = DIM / 32;

    auto load_stage = [&](int buf, int kw0) {
        const uint32_t sb = sbase + (uint32_t)buf * 2 * GARR * 4;
#pragma unroll
        for (int p = 0; p < 4; p++) {
            const int r = lr + p * 32;
            const int widx = r * RSTR + cw4;
            CP16(sb + widx * 4,          Ahg + (m0 + r) * KW + kw0 + cw4);
            CP16(sb + (GARR + widx) * 4, Bhg + (n0 + r) * KW + kw0 + cw4);
        }
    };

    load_stage(0, 0);
    CP_COMMIT();

    for (int kt = 0; kt < NT; kt++) {
        CP_WAIT0();
        __syncthreads();
        if (kt + 1 < NT) {
            load_stage((kt + 1) & 1, (kt + 1) * 16);
            CP_COMMIT();
        }

        const uint32_t* Ah = gsm + (kt & 1) * 2 * GARR;
        const uint32_t* Bh = Ah + GARR;

#pragma unroll
        for (int ck = 0; ck < 2; ck++) {
            const int kwb = ck * 8;
            uint32_t a[4][4];
#pragma unroll
            for (int mi = 0; mi < 4; mi++) {
                const int rb = wm * 64 + mi * 16 + g;
                a[mi][0] = Ah[rb * RSTR + kwb + t];
                a[mi][1] = Ah[(rb + 8) * RSTR + kwb + t];
                a[mi][2] = Ah[rb * RSTR + kwb + t + 4];
                a[mi][3] = Ah[(rb + 8) * RSTR + kwb + t + 4];
            }
#pragma unroll
            for (int nj = 0; nj < 8; nj++) {
                const int cb = wn * 64 + nj * 8 + g;
                uint32_t bh[2];
                bh[0] = Bh[cb * RSTR + kwb + t];
                bh[1] = Bh[cb * RSTR + kwb + t + 4];
#pragma unroll
                for (int mi = 0; mi < 4; mi++) mma16h(acc[mi][nj], a[mi], bh);
            }
        }
    }

    // ---- epilogue ----
    if (Cf) {
#pragma unroll
        for (int mi = 0; mi < 4; mi++) {
#pragma unroll
            for (int nj = 0; nj < 8; nj++) {
                const int row = (int)m0 + wm * 64 + mi * 16 + g;
                const int col = (int)n0 + wn * 64 + nj * 8 + 2 * t;
                *(float2*)(Cf + (size_t)row * DIM + col)       = make_float2(acc[mi][nj][0], acc[mi][nj][1]);
                *(float2*)(Cf + (size_t)(row + 8) * DIM + col) = make_float2(acc[mi][nj][2], acc[mi][nj][3]);
            }
        }
    } else {
        uint32_t* Oh = (blockIdx.z == 0) ? Qh : (blockIdx.z == 1 ? Kh : Vh);
        uint32_t* Ol = (blockIdx.z == 0) ? Ql : nullptr;
#pragma unroll
        for (int mi = 0; mi < 4; mi++) {
#pragma unroll
            for (int nj = 0; nj < 8; nj++) {
                const int row = (int)m0 + wm * 64 + mi * 16 + g;
                const int wc  = (int)(n0 >> 1) + wn * 32 + nj * 4 + t;
                if (Ol) {
                    uint32_t h0, l0, h1, l1;
                    splitpackh(acc[mi][nj][0], acc[mi][nj][1], h0, l0);
                    splitpackh(acc[mi][nj][2], acc[mi][nj][3], h1, l1);
                    Oh[(size_t)row * KW + wc]       = h0;
                    Ol[(size_t)row * KW + wc]       = l0;
                    Oh[(size_t)(row + 8) * KW + wc] = h1;
                    Ol[(size_t)(row + 8) * KW + wc] = l1;
                } else {
                    Oh[(size_t)row * KW + wc]       = pack2h(acc[mi][nj][0], acc[mi][nj][1]);
                    Oh[(size_t)(row + 8) * KW + wc] = pack2h(acc[mi][nj][2], acc[mi][nj][3]);
                }
            }
        }
    }
}

// ---------------- Flash attention (fp16) with diagonal mask ------------------
// QK 2-pass (Q split hi/lo, staged via SMEM as in R12); PV single pass.
// K/V tiles double-buffered: LDG-prefetch regs -> compute -> STS -> 1 sync.
#define BQ 128
#define BS 64
#define QS 36
#define KS 36
#define VS 72
#define KBUF (BS * KS)   // 2304 words per K buffer
#define VBUF (32 * VS)   // 2304 words per V buffer
#define ATTN_SMEM_WORDS (2 * BQ * QS + 2 * KBUF + 2 * VBUF)
#define ATTN_SMEM_BYTES (ATTN_SMEM_WORDS * 4)   // 73728

__global__ void __launch_bounds__(256, 2)
attn_kernel(const uint32_t* __restrict__ Qhg, const uint32_t* __restrict__ Qlg,
            const uint32_t* __restrict__ Khg, const uint32_t* __restrict__ Vhg,
            uint32_t* __restrict__ Ohg)
{
    extern __shared__ uint32_t smw[];
    uint32_t* Qh  = smw;                    // [128][QS]
    uint32_t* Ql  = Qh + BQ * QS;
    uint32_t* Kb  = Ql + BQ * QS;           // 2 x [64][KS]
    uint32_t* Vb  = Kb + 2 * KBUF;          // 2 x [32][VS]

    const int tid  = threadIdx.x;
    const int lane = tid & 31;
    const int wid  = tid >> 5;
    const int g    = lane >> 2;
    const int t    = lane & 3;
    const int tx   = tid & 15;
    const int ty   = tid >> 4;
    const int q0   = blockIdx.x * BQ;
    const int bh_i = blockIdx.y;
    const int b    = bh_i >> 4;
    const int h    = bh_i & 15;
    const float scale = 0.125f;

    const size_t rowbase = (size_t)b * SEQLEN;
    const int hw = h * 32;

    // loader lane mapping
    const int kr_r  = tid >> 2;          // K: row 0..63
    const int kr_cw = (tid & 3) * 8;     // K: 8 words
    const int v_s2  = tid >> 3;          // V: sword 0..31
    const int v_db  = (tid & 7) * 8;     // V: d offset

    // ---- load packed Q tile [BQ][32 words] hi+lo ----
#pragma unroll
    for (int rr = 0; rr < 8; rr++) {
        const int r = ty + rr * 16;
        const size_t gidx = (rowbase + q0 + r) * KW + hw + tx * 2;
        *(uint2*)&Qh[r * QS + tx * 2] = *(const uint2*)(Qhg + gidx);
        *(uint2*)&Ql[r * QS + tx * 2] = *(const uint2*)(Qlg + gidx);
    }

    float mrow[2], lrow[2], O[8][4];
    mrow[0] = mrow[1] = -1e30f;
    lrow[0] = lrow[1] = 0.f;
#pragma unroll
    for (int nt = 0; nt < 8; nt++)
#pragma unroll
        for (int c = 0; c < 4; c++) O[nt][c] = 0.f;

    const int rq = wid * 16;

    // ---- tile 0 load + store to buffer 0 ----
    {
        const uint32_t* kr = Khg + (rowbase + kr_r) * KW + hw + kr_cw;
        uint4 k0 = *(const uint4*)kr;
        uint4 k1 = *(const uint4*)(kr + 4);
        const uint32_t* vp = Vhg + (rowbase + 2 * v_s2) * KW + hw + v_db / 2;
        uint4 w0 = *(const uint4*)vp;
        uint4 w1 = *(const uint4*)(vp + KW);
        *(uint4*)&Kb[kr_r * KS + kr_cw]     = k0;
        *(uint4*)&Kb[kr_r * KS + kr_cw + 4] = k1;
        uint4 o0, o1;
        o0.x = prmtw(w0.x, w1.x, 0x5410); o0.y = prmtw(w0.x, w1.x, 0x7632);
        o0.z = prmtw(w0.y, w1.y, 0x5410); o0.w = prmtw(w0.y, w1.y, 0x7632);
        o1.x = prmtw(w0.z, w1.z, 0x5410); o1.y = prmtw(w0.z, w1.z, 0x7632);
        o1.z = prmtw(w0.w, w1.w, 0x5410); o1.w = prmtw(w0.w, w1.w, 0x7632);
        *(uint4*)&Vb[v_s2 * VS + v_db]     = o0;
        *(uint4*)&Vb[v_s2 * VS + v_db + 4] = o1;
    }
    __syncthreads();

    const int NTILES = SEQLEN / BS;
    for (int it = 0; it < NTILES; it++) {
        const int s0 = it * BS;
        const bool has = (it + 1 < NTILES);
        const uint32_t* Khi = Kb + (it & 1) * KBUF;
        const uint32_t* Vhi = Vb + (it & 1) * VBUF;

        // prefetch next tile into registers (overlaps with compute)
        uint4 nk0, nk1, nw0, nw1;
        if (has) {
            const uint32_t* kr = Khg + (rowbase + s0 + BS + kr_r) * KW + hw + kr_cw;
            nk0 = *(const uint4*)kr;
            nk1 = *(const uint4*)(kr + 4);
            const uint32_t* vp = Vhg + (rowbase + s0 + BS + 2 * v_s2) * KW + hw + v_db / 2;
            nw0 = *(const uint4*)vp;
            nw1 = *(const uint4*)(vp + KW);
        }

        // ---- S = Q @ K^T  (2-pass: Q hi + Q lo) ----
        float S[8][4];
#pragma unroll
        for (int nt = 0; nt < 8; nt++)
#pragma unroll
            for (int c = 0; c < 4; c++) S[nt][c] = 0.f;

#pragma unroll
        for (int ks = 0; ks < 4; ks++) {
            const int kwb = ks * 8;
            uint32_t ah[4], al[4], bfr[8][2];
            ah[0] = Qh[(rq + g) * QS + kwb + t];
            ah[1] = Qh[(rq + g + 8) * QS + kwb + t];
            ah[2] = Qh[(rq + g) * QS + kwb + t + 4];
            ah[3] = Qh[(rq + g + 8) * QS + kwb + t + 4];
            al[0] = Ql[(rq + g) * QS + kwb + t];
            al[1] = Ql[(rq + g + 8) * QS + kwb + t];
            al[2] = Ql[(rq + g) * QS + kwb + t + 4];
            al[3] = Ql[(rq + g + 8) * QS + kwb + t + 4];
#pragma unroll
            for (int nt = 0; nt < 8; nt++) {
                bfr[nt][0] = Khi[(nt * 8 + g) * KS + kwb + t];
                bfr[nt][1] = Khi[(nt * 8 + g) * KS + kwb + t + 4];
                mma16h(S[nt], ah, bfr[nt]);
            }
#pragma unroll
            for (int nt = 0; nt < 8; nt++)
                mma16h(S[nt], al, bfr[nt]);
        }

        // ---- scale + diagonal mask ----
#pragma unroll
        for (int nt = 0; nt < 8; nt++) {
#pragma unroll
            for (int c = 0; c < 4; c++) {
                const int col = s0 + nt * 8 + 2 * t + (c & 1);
                const int row = q0 + rq + g + ((c >= 2) ? 8 : 0);
                float s = S[nt][c] * scale;
                if (col == row) s = -1e30f;
                S[nt][c] = s;
            }
        }

        // ---- online softmax ----
        float mx0 = -1e30f, mx1 = -1e30f;
#pragma unroll
        for (int nt = 0; nt < 8; nt++) {
            mx0 = fmaxf(mx0, fmaxf(S[nt][0], S[nt][1]));
            mx1 = fmaxf(mx1, fmaxf(S[nt][2], S[nt][3]));
        }
        mx0 = fmaxf(mx0, __shfl_xor_sync(0xffffffffu, mx0, 1));
        mx0 = fmaxf(mx0, __shfl_xor_sync(0xffffffffu, mx0, 2));
        mx1 = fmaxf(mx1, __shfl_xor_sync(0xffffffffu, mx1, 1));
        mx1 = fmaxf(mx1, __shfl_xor_sync(0xffffffffu, mx1, 2));

        const float mn0 = fmaxf(mrow[0], mx0);
        const float mn1 = fmaxf(mrow[1], mx1);
        const float corr0 = __expf(mrow[0] - mn0);
        const float corr1 = __expf(mrow[1] - mn1);
        mrow[0] = mn0; mrow[1] = mn1;

        float rs0 = 0.f, rs1 = 0.f;
#pragma unroll
        for (int nt = 0; nt < 8; nt++) {
            float p0 = __expf(S[nt][0] - mn0);
            float p1 = __expf(S[nt][1] - mn0);
            float p2 = __expf(S[nt][2] - mn1);
            float p3 = __expf(S[nt][3] - mn1);
            S[nt][0] = p0; S[nt][1] = p1; S[nt][2] = p2; S[nt][3] = p3;
            rs0 += p0 + p1;
            rs1 += p2 + p3;
        }
        rs0 += __shfl_xor_sync(0xffffffffu, rs0, 1);
        rs0 += __shfl_xor_sync(0xffffffffu, rs0, 2);
        rs1 += __shfl_xor_sync(0xffffffffu, rs1, 1);
        rs1 += __shfl_xor_sync(0xffffffffu, rs1, 2);

        lrow[0] = lrow[0] * corr0 + rs0;
        lrow[1] = lrow[1] * corr1 + rs1;
#pragma unroll
        for (int nt = 0; nt < 8; nt++) {
            O[nt][0] *= corr0; O[nt][1] *= corr0;
            O[nt][2] *= corr1; O[nt][3] *= corr1;
        }

        // ---- O += P @ V : single pass (P hi only) ----
#pragma unroll
        for (int ks = 0; ks < 4; ks++) {
            uint32_t ph[4];
            ph[0] = pack2h(S[2 * ks][0],     S[2 * ks][1]);
            ph[1] = pack2h(S[2 * ks][2],     S[2 * ks][3]);
            ph[2] = pack2h(S[2 * ks + 1][0], S[2 * ks + 1][1]);
            ph[3] = pack2h(S[2 * ks + 1][2], S[2 * ks + 1][3]);
            const int swb = ks * 8;
#pragma unroll
            for (int nt = 0; nt < 8; nt++) {
                uint32_t vfr[2];
                vfr[0] = Vhi[(swb + t) * VS + nt * 8 + g];
                vfr[1] = Vhi[(swb + t + 4) * VS + nt * 8 + g];
                mma16h(O[nt], ph, vfr);
            }
        }

        // ---- store prefetched tile into the other buffer ----
        if (has) {
            uint32_t* Kn = Kb + ((it + 1) & 1) * KBUF;
            uint32_t* Vn = Vb + ((it + 1) & 1) * VBUF;
            *(uint4*)&Kn[kr_r * KS + kr_cw]     = nk0;
            *(uint4*)&Kn[kr_r * KS + kr_cw + 4] = nk1;
            uint4 o0, o1;
            o0.x = prmtw(nw0.x, nw1.x, 0x5410); o0.y = prmtw(nw0.x, nw1.x, 0x7632);
            o0.z = prmtw(nw0.y, nw1.y, 0x5410); o0.w = prmtw(nw0.y, nw1.y, 0x7632);
            o1.x = prmtw(nw0.z, nw1.z, 0x5410); o1.y = prmtw(nw0.z, nw1.z, 0x7632);
            o1.z = prmtw(nw0.w, nw1.w, 0x5410); o1.w = prmtw(nw0.w, nw1.w, 0x7632);
            *(uint4*)&Vn[v_s2 * VS + v_db]     = o0;
            *(uint4*)&Vn[v_s2 * VS + v_db + 4] = o1;
        }
        __syncthreads();
    }

    // ---- finalize: write packed fp16 hi words for wo GEMM ----
    const float inv0 = 1.f / lrow[0];
    const float inv1 = 1.f / lrow[1];
#pragma unroll
    for (int nt = 0; nt < 8; nt++) {
        const int row = q0 + rq + g;
        const int wc  = hw + nt * 4 + t;
        Ohg[(rowbase + row) * KW + wc]     = pack2h(O[nt][0] * inv0, O[nt][1] * inv0);
        Ohg[(rowbase + row + 8) * KW + wc] = pack2h(O[nt][2] * inv1, O[nt][3] * inv1);
    }
}

// ---------------- launch ------------------------------------------------------
extern "C" void kernel_launch(void* const* d_in, const int* in_sizes, int n_in,
                              void* d_out, int out_size)
{
    (void)in_sizes; (void)n_in; (void)out_size;
    const float* x  = (const float*)d_in[0];
    const float* wq = (const float*)d_in[1];
    const float* wk = (const float*)d_in[2];
    const float* wv = (const float*)d_in[3];
    const float* wo = (const float*)d_in[4];
    float* out = (float*)d_out;

    uint32_t *xh, *qh, *ql, *kh, *vh, *ah;
    uint32_t *wqh, *wkh, *wvh, *woh;
    cudaGetSymbolAddress((void**)&xh, g_xh);
    cudaGetSymbolAddress((void**)&qh, g_qh);  cudaGetSymbolAddress((void**)&ql, g_ql);
    cudaGetSymbolAddress((void**)&kh, g_kh);  cudaGetSymbolAddress((void**)&vh, g_vh);
    cudaGetSymbolAddress((void**)&ah, g_ah);
    cudaGetSymbolAddress((void**)&wqh, g_wqh);
    cudaGetSymbolAddress((void**)&wkh, g_wkh);
    cudaGetSymbolAddress((void**)&wvh, g_wvh);
    cudaGetSymbolAddress((void**)&woh, g_woh);

    cudaFuncSetAttribute(gemm_h, cudaFuncAttributeMaxDynamicSharedMemorySize, GEMM_SMEM_BYTES);
    cudaFuncSetAttribute(attn_kernel, cudaFuncAttributeMaxDynamicSharedMemorySize, ATTN_SMEM_BYTES);

    // 0) prepack x + weights (all hi-only)
    prepack_hi<<<1024, 256>>>(x, xh, MTOT * KW);
    prepack_hi<<<256, 256>>>(wq, wqh, DIM * KW);
    prepack_hi<<<256, 256>>>(wk, wkh, DIM * KW);
    prepack_hi<<<256, 256>>>(wv, wvh, DIM * KW);
    prepack_hi<<<256, 256>>>(wo, woh, DIM * KW);

    // 1) QKV projections, single-pass B (fused via grid.z)
    {
        dim3 grid(DIM / 128, MTOT / 128, 3);
        gemm_h<<<grid, 128, GEMM_SMEM_BYTES>>>(xh,
                                               wqh, wkh, wvh,
                                               qh, ql, kh, vh, nullptr);
    }
    // 2) attention (packed in, packed out)
    {
        dim3 grid(SEQLEN / BQ, BATCH * NHEADS);
        attn_kernel<<<grid, 256, ATTN_SMEM_BYTES>>>(qh, ql, kh, vh, ah);
    }
    // 3) output projection, single-pass B -> fp32 out
    {
        dim3 grid(DIM / 128, MTOT / 128, 1);
        gemm_h<<<grid, 128, GEMM_SMEM_BYTES>>>(ah,
                                               woh, woh, woh,
                                               nullptr, nullptr, nullptr, nullptr,
                                               out);
    }
}

// round 16
// speedup vs baseline: 6.8015x; 1.1339x over previous
#include <cuda_runtime.h>
#include <cuda_fp16.h>
#include <math.h>
#include <stdint.h>

#define BATCH   4
#define SEQLEN  2048
#define NHEADS  16
#define HDIM    64
#define DIM     1024
#define MTOT    (BATCH * SEQLEN)   // 8192
#define KW      (DIM / 2)          // 512 packed words per token row

// ---------------- scratch (static __device__, no allocs allowed) -------------
__device__ uint32_t g_xh[MTOT * KW];                 // x (A-side, hi only)
__device__ uint32_t g_qh[MTOT * KW];                 // Q hi only
__device__ uint32_t g_kh[MTOT * KW];                 // K hi only
__device__ uint32_t g_vh[MTOT * KW];                 // V hi only
__device__ uint32_t g_ah[MTOT * KW];                 // attn out (A-side, hi only)
__device__ uint32_t g_wqh[DIM * KW];                 // all weights: hi only
__device__ uint32_t g_wkh[DIM * KW];
__device__ uint32_t g_wvh[DIM * KW];
__device__ uint32_t g_woh[DIM * KW];

// ---------------- fp16x2 helpers ---------------------------------------------
__device__ __forceinline__ uint32_t pack2h(float lo, float hi) {
    uint32_t r;
    asm("cvt.rn.f16x2.f32 %0, %1, %2;" : "=r"(r) : "f"(hi), "f"(lo));
    return r;
}
__device__ __forceinline__ uint32_t prmtw(uint32_t a, uint32_t b, uint32_t sel) {
    uint32_t d;
    asm("prmt.b32 %0, %1, %2, %3;" : "=r"(d) : "r"(a), "r"(b), "r"(sel));
    return d;
}
__device__ __forceinline__ void mma16h(float* d, const uint32_t* a, const uint32_t* b) {
    asm volatile(
        "mma.sync.aligned.m16n8k16.row.col.f32.f16.f16.f32 "
        "{%0,%1,%2,%3}, {%4,%5,%6,%7}, {%8,%9}, {%0,%1,%2,%3};"
        : "+f"(d[0]), "+f"(d[1]), "+f"(d[2]), "+f"(d[3])
        : "r"(a[0]), "r"(a[1]), "r"(a[2]), "r"(a[3]), "r"(b[0]), "r"(b[1]));
}
__device__ __forceinline__ uint32_t smem_u32(const void* p) {
    uint32_t a;
    asm("{ .reg .u64 t; cvta.to.shared.u64 t, %1; cvt.u32.u64 %0, t; }" : "=r"(a) : "l"(p));
    return a;
}
#define CP16(saddr, gptr) \
    asm volatile("cp.async.cg.shared.global [%0], [%1], 16;" :: "r"(saddr), "l"(gptr))
#define CP_COMMIT() asm volatile("cp.async.commit_group;" ::: "memory")
#define CP_WAIT0()  asm volatile("cp.async.wait_group 0;" ::: "memory")

// ---------------- prepack kernel ----------------------------------------------
__global__ void prepack_hi(const float* __restrict__ src, uint32_t* __restrict__ hi, int nwords)
{
    int i = blockIdx.x * blockDim.x + threadIdx.x;
    int stride = gridDim.x * blockDim.x;
    for (; i < nwords; i += stride) {
        float2 v = ((const float2*)src)[i];
        hi[i] = pack2h(v.x, v.y);
    }
}

// ---------------- GEMM: C[m][n] = sum_k A[m][k]*B[n][k]  (NT) ----------------
// CTA 128x128x32, 4 warps of 64x64. A and B both fp16 hi-only (single pass).
#define RSTR 20                          // words/row: 16 kwords + 4 pad
#define GARR (128 * RSTR)                // 2560 words per array
#define GEMM_SMEM_BYTES (2 * 2 * GARR * 4)   // 40960

__global__ void __launch_bounds__(128, 3)
gemm_h(const uint32_t* __restrict__ Ahg,
       const uint32_t* __restrict__ Bh0, const uint32_t* __restrict__ Bh1,
       const uint32_t* __restrict__ Bh2,
       uint32_t* __restrict__ O0, uint32_t* __restrict__ O1, uint32_t* __restrict__ O2,
       float* __restrict__ Cf)
{
    const uint32_t* Bhg = (blockIdx.z == 0) ? Bh0 : (blockIdx.z == 1 ? Bh1 : Bh2);

    extern __shared__ uint32_t gsm[];
    const uint32_t sbase = smem_u32(gsm);
    const int tid  = threadIdx.x;
    const int lane = tid & 31;
    const int wid  = tid >> 5;
    const int g    = lane >> 2;
    const int t    = lane & 3;
    const int wm   = wid >> 1;
    const int wn   = wid & 1;
    const size_t m0 = blockIdx.y * 128;
    const size_t n0 = blockIdx.x * 128;

    const int lr  = tid >> 2;            // 0..31
    const int cw4 = (tid & 3) * 4;       // kword offset

    float acc[4][8][4];
#pragma unroll
    for (int i = 0; i < 4; i++)
#pragma unroll
        for (int j = 0; j < 8; j++)
#pragma unroll
            for (int c = 0; c < 4; c++) acc[i][j][c] = 0.f;

    const int NT = DIM / 32;

    auto load_stage = [&](int buf, int kw0) {
        const uint32_t sb = sbase + (uint32_t)buf * 2 * GARR * 4;
#pragma unroll
        for (int p = 0; p < 4; p++) {
            const int r = lr + p * 32;
            const int widx = r * RSTR + cw4;
            CP16(sb + widx * 4,          Ahg + (m0 + r) * KW + kw0 + cw4);
            CP16(sb + (GARR + widx) * 4, Bhg + (n0 + r) * KW + kw0 + cw4);
        }
    };

    load_stage(0, 0);
    CP_COMMIT();

    for (int kt = 0; kt < NT; kt++) {
        CP_WAIT0();
        __syncthreads();
        if (kt + 1 < NT) {
            load_stage((kt + 1) & 1, (kt + 1) * 16);
            CP_COMMIT();
        }

        const uint32_t* Ah = gsm + (kt & 1) * 2 * GARR;
        const uint32_t* Bh = Ah + GARR;

#pragma unroll
        for (int ck = 0; ck < 2; ck++) {
            const int kwb = ck * 8;
            uint32_t a[4][4];
#pragma unroll
            for (int mi = 0; mi < 4; mi++) {
                const int rb = wm * 64 + mi * 16 + g;
                a[mi][0] = Ah[rb * RSTR + kwb + t];
                a[mi][1] = Ah[(rb + 8) * RSTR + kwb + t];
                a[mi][2] = Ah[rb * RSTR + kwb + t + 4];
                a[mi][3] = Ah[(rb + 8) * RSTR + kwb + t + 4];
            }
#pragma unroll
            for (int nj = 0; nj < 8; nj++) {
                const int cb = wn * 64 + nj * 8 + g;
                uint32_t bh[2];
                bh[0] = Bh[cb * RSTR + kwb + t];
                bh[1] = Bh[cb * RSTR + kwb + t + 4];
#pragma unroll
                for (int mi = 0; mi < 4; mi++) mma16h(acc[mi][nj], a[mi], bh);
            }
        }
    }

    // ---- epilogue ----
    if (Cf) {
#pragma unroll
        for (int mi = 0; mi < 4; mi++) {
#pragma unroll
            for (int nj = 0; nj < 8; nj++) {
                const int row = (int)m0 + wm * 64 + mi * 16 + g;
                const int col = (int)n0 + wn * 64 + nj * 8 + 2 * t;
                *(float2*)(Cf + (size_t)row * DIM + col)       = make_float2(acc[mi][nj][0], acc[mi][nj][1]);
                *(float2*)(Cf + (size_t)(row + 8) * DIM + col) = make_float2(acc[mi][nj][2], acc[mi][nj][3]);
            }
        }
    } else {
        uint32_t* Oh = (blockIdx.z == 0) ? O0 : (blockIdx.z == 1 ? O1 : O2);
#pragma unroll
        for (int mi = 0; mi < 4; mi++) {
#pragma unroll
            for (int nj = 0; nj < 8; nj++) {
                const int row = (int)m0 + wm * 64 + mi * 16 + g;
                const int wc  = (int)(n0 >> 1) + wn * 32 + nj * 4 + t;
                Oh[(size_t)row * KW + wc]       = pack2h(acc[mi][nj][0], acc[mi][nj][1]);
                Oh[(size_t)(row + 8) * KW + wc] = pack2h(acc[mi][nj][2], acc[mi][nj][3]);
            }
        }
    }
}

// ---------------- Flash attention (plain fp16 mma) with diagonal mask --------
// QK single pass, Q fragments REGISTER-RESIDENT (loaded once from gmem).
// PV single pass (P hi only). K/V double-buffered, one sync per tile.
#define BQ 128
#define BS 64
#define KS 36
#define VS 72
#define KBUF (BS * KS)   // 2304 words per K buffer
#define VBUF (32 * VS)   // 2304 words per V buffer
#define ATTN_SMEM_WORDS (2 * KBUF + 2 * VBUF)
#define ATTN_SMEM_BYTES (ATTN_SMEM_WORDS * 4)   // 36864

__global__ void __launch_bounds__(256, 2)
attn_kernel(const uint32_t* __restrict__ Qhg,
            const uint32_t* __restrict__ Khg, const uint32_t* __restrict__ Vhg,
            uint32_t* __restrict__ Ohg)
{
    extern __shared__ uint32_t smw[];
    uint32_t* Kb = smw;                     // 2 x [64][KS]
    uint32_t* Vb = Kb + 2 * KBUF;           // 2 x [32][VS]

    const int tid  = threadIdx.x;
    const int lane = tid & 31;
    const int wid  = tid >> 5;
    const int g    = lane >> 2;
    const int t    = lane & 3;
    const int q0   = blockIdx.x * BQ;
    const int bh_i = blockIdx.y;
    const int b    = bh_i >> 4;
    const int h    = bh_i & 15;
    const float scale = 0.125f;

    const size_t rowbase = (size_t)b * SEQLEN;
    const int hw = h * 32;

    // loader lane mapping
    const int kr_r  = tid >> 2;          // K: row 0..63
    const int kr_cw = (tid & 3) * 8;     // K: 8 words
    const int v_s2  = tid >> 3;          // V: sword 0..31
    const int v_db  = (tid & 7) * 8;     // V: d offset

    const int rq = wid * 16;

    // ---- Q fragments: register-resident hi-only, loaded once from gmem ----
    uint32_t qf[4][4];
    {
        const size_t r0 = (rowbase + q0 + rq + g) * KW + hw;
        const size_t r1 = (rowbase + q0 + rq + g + 8) * KW + hw;
#pragma unroll
        for (int ks = 0; ks < 4; ks++) {
            const int kwb = ks * 8;
            qf[ks][0] = Qhg[r0 + kwb + t];
            qf[ks][1] = Qhg[r1 + kwb + t];
            qf[ks][2] = Qhg[r0 + kwb + t + 4];
            qf[ks][3] = Qhg[r1 + kwb + t + 4];
        }
    }

    float mrow[2], lrow[2], O[8][4];
    mrow[0] = mrow[1] = -1e30f;
    lrow[0] = lrow[1] = 0.f;
#pragma unroll
    for (int nt = 0; nt < 8; nt++)
#pragma unroll
        for (int c = 0; c < 4; c++) O[nt][c] = 0.f;

    // ---- tile 0 load + store to buffer 0 ----
    {
        const uint32_t* kr = Khg + (rowbase + kr_r) * KW + hw + kr_cw;
        uint4 k0 = *(const uint4*)kr;
        uint4 k1 = *(const uint4*)(kr + 4);
        const uint32_t* vp = Vhg + (rowbase + 2 * v_s2) * KW + hw + v_db / 2;
        uint4 w0 = *(const uint4*)vp;
        uint4 w1 = *(const uint4*)(vp + KW);
        *(uint4*)&Kb[kr_r * KS + kr_cw]     = k0;
        *(uint4*)&Kb[kr_r * KS + kr_cw + 4] = k1;
        uint4 o0, o1;
        o0.x = prmtw(w0.x, w1.x, 0x5410); o0.y = prmtw(w0.x, w1.x, 0x7632);
        o0.z = prmtw(w0.y, w1.y, 0x5410); o0.w = prmtw(w0.y, w1.y, 0x7632);
        o1.x = prmtw(w0.z, w1.z, 0x5410); o1.y = prmtw(w0.z, w1.z, 0x7632);
        o1.z = prmtw(w0.w, w1.w, 0x5410); o1.w = prmtw(w0.w, w1.w, 0x7632);
        *(uint4*)&Vb[v_s2 * VS + v_db]     = o0;
        *(uint4*)&Vb[v_s2 * VS + v_db + 4] = o1;
    }
    __syncthreads();

    const int NTILES = SEQLEN / BS;
    for (int it = 0; it < NTILES; it++) {
        const int s0 = it * BS;
        const bool has = (it + 1 < NTILES);
        const uint32_t* Khi = Kb + (it & 1) * KBUF;
        const uint32_t* Vhi = Vb + (it & 1) * VBUF;

        // prefetch next tile into registers (overlaps with compute)
        uint4 nk0, nk1, nw0, nw1;
        if (has) {
            const uint32_t* kr = Khg + (rowbase + s0 + BS + kr_r) * KW + hw + kr_cw;
            nk0 = *(const uint4*)kr;
            nk1 = *(const uint4*)(kr + 4);
            const uint32_t* vp = Vhg + (rowbase + s0 + BS + 2 * v_s2) * KW + hw + v_db / 2;
            nw0 = *(const uint4*)vp;
            nw1 = *(const uint4*)(vp + KW);
        }

        // ---- S = Q @ K^T  (single pass, Q frags in registers) ----
        float S[8][4];
#pragma unroll
        for (int nt = 0; nt < 8; nt++)
#pragma unroll
            for (int c = 0; c < 4; c++) S[nt][c] = 0.f;

#pragma unroll
        for (int ks = 0; ks < 4; ks++) {
            const int kwb = ks * 8;
#pragma unroll
            for (int nt = 0; nt < 8; nt++) {
                uint32_t bfr[2];
                bfr[0] = Khi[(nt * 8 + g) * KS + kwb + t];
                bfr[1] = Khi[(nt * 8 + g) * KS + kwb + t + 4];
                mma16h(S[nt], qf[ks], bfr);
            }
        }

        // ---- scale + diagonal mask ----
#pragma unroll
        for (int nt = 0; nt < 8; nt++) {
#pragma unroll
            for (int c = 0; c < 4; c++) {
                const int col = s0 + nt * 8 + 2 * t + (c & 1);
                const int row = q0 + rq + g + ((c >= 2) ? 8 : 0);
                float s = S[nt][c] * scale;
                if (col == row) s = -1e30f;
                S[nt][c] = s;
            }
        }

        // ---- online softmax ----
        float mx0 = -1e30f, mx1 = -1e30f;
#pragma unroll
        for (int nt = 0; nt < 8; nt++) {
            mx0 = fmaxf(mx0, fmaxf(S[nt][0], S[nt][1]));
            mx1 = fmaxf(mx1, fmaxf(S[nt][2], S[nt][3]));
        }
        mx0 = fmaxf(mx0, __shfl_xor_sync(0xffffffffu, mx0, 1));
        mx0 = fmaxf(mx0, __shfl_xor_sync(0xffffffffu, mx0, 2));
        mx1 = fmaxf(mx1, __shfl_xor_sync(0xffffffffu, mx1, 1));
        mx1 = fmaxf(mx1, __shfl_xor_sync(0xffffffffu, mx1, 2));

        const float mn0 = fmaxf(mrow[0], mx0);
        const float mn1 = fmaxf(mrow[1], mx1);
        const float corr0 = __expf(mrow[0] - mn0);
        const float corr1 = __expf(mrow[1] - mn1);
        mrow[0] = mn0; mrow[1] = mn1;

        float rs0 = 0.f, rs1 = 0.f;
#pragma unroll
        for (int nt = 0; nt < 8; nt++) {
            float p0 = __expf(S[nt][0] - mn0);
            float p1 = __expf(S[nt][1] - mn0);
            float p2 = __expf(S[nt][2] - mn1);
            float p3 = __expf(S[nt][3] - mn1);
            S[nt][0] = p0; S[nt][1] = p1; S[nt][2] = p2; S[nt][3] = p3;
            rs0 += p0 + p1;
            rs1 += p2 + p3;
        }
        rs0 += __shfl_xor_sync(0xffffffffu, rs0, 1);
        rs0 += __shfl_xor_sync(0xffffffffu, rs0, 2);
        rs1 += __shfl_xor_sync(0xffffffffu, rs1, 1);
        rs1 += __shfl_xor_sync(0xffffffffu, rs1, 2);

        lrow[0] = lrow[0] * corr0 + rs0;
        lrow[1] = lrow[1] * corr1 + rs1;
#pragma unroll
        for (int nt = 0; nt < 8; nt++) {
            O[nt][0] *= corr0; O[nt][1] *= corr0;
            O[nt][2] *= corr1; O[nt][3] *= corr1;
        }

        // ---- O += P @ V : single pass (P hi only) ----
#pragma unroll
        for (int ks = 0; ks < 4; ks++) {
            uint32_t ph[4];
            ph[0] = pack2h(S[2 * ks][0],     S[2 * ks][1]);
            ph[1] = pack2h(S[2 * ks][2],     S[2 * ks][3]);
            ph[2] = pack2h(S[2 * ks + 1][0], S[2 * ks + 1][1]);
            ph[3] = pack2h(S[2 * ks + 1][2], S[2 * ks + 1][3]);
            const int swb = ks * 8;
#pragma unroll
            for (int nt = 0; nt < 8; nt++) {
                uint32_t vfr[2];
                vfr[0] = Vhi[(swb + t) * VS + nt * 8 + g];
                vfr[1] = Vhi[(swb + t + 4) * VS + nt * 8 + g];
                mma16h(O[nt], ph, vfr);
            }
        }

        // ---- store prefetched tile into the other buffer ----
        if (has) {
            uint32_t* Kn = Kb + ((it + 1) & 1) * KBUF;
            uint32_t* Vn = Vb + ((it + 1) & 1) * VBUF;
            *(uint4*)&Kn[kr_r * KS + kr_cw]     = nk0;
            *(uint4*)&Kn[kr_r * KS + kr_cw + 4] = nk1;
            uint4 o0, o1;
            o0.x = prmtw(nw0.x, nw1.x, 0x5410); o0.y = prmtw(nw0.x, nw1.x, 0x7632);
            o0.z = prmtw(nw0.y, nw1.y, 0x5410); o0.w = prmtw(nw0.y, nw1.y, 0x7632);
            o1.x = prmtw(nw0.z, nw1.z, 0x5410); o1.y = prmtw(nw0.z, nw1.z, 0x7632);
            o1.z = prmtw(nw0.w, nw1.w, 0x5410); o1.w = prmtw(nw0.w, nw1.w, 0x7632);
            *(uint4*)&Vn[v_s2 * VS + v_db]     = o0;
            *(uint4*)&Vn[v_s2 * VS + v_db + 4] = o1;
        }
        __syncthreads();
    }

    // ---- finalize: write packed fp16 hi words for wo GEMM ----
    const float inv0 = 1.f / lrow[0];
    const float inv1 = 1.f / lrow[1];
#pragma unroll
    for (int nt = 0; nt < 8; nt++) {
        const int row = q0 + rq + g;
        const int wc  = hw + nt * 4 + t;
        Ohg[(rowbase + row) * KW + wc]     = pack2h(O[nt][0] * inv0, O[nt][1] * inv0);
        Ohg[(rowbase + row + 8) * KW + wc] = pack2h(O[nt][2] * inv1, O[nt][3] * inv1);
    }
}

// ---------------- launch ------------------------------------------------------
extern "C" void kernel_launch(void* const* d_in, const int* in_sizes, int n_in,
                              void* d_out, int out_size)
{
    (void)in_sizes; (void)n_in; (void)out_size;
    const float* x  = (const float*)d_in[0];
    const float* wq = (const float*)d_in[1];
    const float* wk = (const float*)d_in[2];
    const float* wv = (const float*)d_in[3];
    const float* wo = (const float*)d_in[4];
    float* out = (float*)d_out;

    uint32_t *xh, *qh, *kh, *vh, *ah;
    uint32_t *wqh, *wkh, *wvh, *woh;
    cudaGetSymbolAddress((void**)&xh, g_xh);
    cudaGetSymbolAddress((void**)&qh, g_qh);
    cudaGetSymbolAddress((void**)&kh, g_kh);  cudaGetSymbolAddress((void**)&vh, g_vh);
    cudaGetSymbolAddress((void**)&ah, g_ah);
    cudaGetSymbolAddress((void**)&wqh, g_wqh);
    cudaGetSymbolAddress((void**)&wkh, g_wkh);
    cudaGetSymbolAddress((void**)&wvh, g_wvh);
    cudaGetSymbolAddress((void**)&woh, g_woh);

    cudaFuncSetAttribute(gemm_h, cudaFuncAttributeMaxDynamicSharedMemorySize, GEMM_SMEM_BYTES);
    cudaFuncSetAttribute(attn_kernel, cudaFuncAttributeMaxDynamicSharedMemorySize, ATTN_SMEM_BYTES);

    // 0) prepack x + weights (all hi-only)
    prepack_hi<<<1024, 256>>>(x, xh, MTOT * KW);
    prepack_hi<<<256, 256>>>(wq, wqh, DIM * KW);
    prepack_hi<<<256, 256>>>(wk, wkh, DIM * KW);
    prepack_hi<<<256, 256>>>(wv, wvh, DIM * KW);
    prepack_hi<<<256, 256>>>(wo, woh, DIM * KW);

    // 1) QKV projections, single-pass B (fused via grid.z)
    {
        dim3 grid(DIM / 128, MTOT / 128, 3);
        gemm_h<<<grid, 128, GEMM_SMEM_BYTES>>>(xh,
                                               wqh, wkh, wvh,
                                               qh, kh, vh, nullptr);
    }
    // 2) attention (packed in, packed out)
    {
        dim3 grid(SEQLEN / BQ, BATCH * NHEADS);
        attn_kernel<<<grid, 256, ATTN_SMEM_BYTES>>>(qh, kh, vh, ah);
    }
    // 3) output projection, single-pass B -> fp32 out
    {
        dim3 grid(DIM / 128, MTOT / 128, 1);
        gemm_h<<<grid, 128, GEMM_SMEM_BYTES>>>(ah,
                                               woh, woh, woh,
                                               nullptr, nullptr, nullptr,
                                               out);
    }
}